// round 8
// baseline (speedup 1.0000x reference)
#include <cuda_runtime.h>
#include <cuda_fp16.h>
#include <math.h>

#define B 64
#define C 256

typedef unsigned long long u64;
typedef unsigned int u32;

// ---------------- f32x2 packed-math helpers ----------------
__device__ __forceinline__ u64 pack2(float lo, float hi){
    u64 r; asm("mov.b64 %0, {%1, %2};" : "=l"(r) : "f"(lo), "f"(hi)); return r;
}
__device__ __forceinline__ u64 dup2(float v){
    u64 r; asm("mov.b64 %0, {%1, %1};" : "=l"(r) : "f"(v)); return r;
}
__device__ __forceinline__ void fma2(u64 &d, u64 a, u64 b){
    asm("fma.rn.f32x2 %0, %1, %2, %0;" : "+l"(d) : "l"(a), "l"(b));
}
__device__ __forceinline__ u64 add2(u64 a, u64 b){
    u64 d; asm("add.rn.f32x2 %0, %1, %2;" : "=l"(d) : "l"(a), "l"(b)); return d;
}
__device__ __forceinline__ float2 unpk(u64 v){
    float2 f; asm("mov.b64 {%0, %1}, %2;" : "=f"(f.x), "=f"(f.y) : "l"(v)); return f;
}
__device__ __forceinline__ u32 h2pack(__half a, __half b){
    return ((u32)__half_as_ushort(b) << 16) | (u32)__half_as_ushort(a);
}

// ---------------- scratch ----------------
__device__ float g_lf[B*C*7*7];
__device__ float g_mf[B*C*5*5];
__device__ float g_sf[B*C*3*3];
__device__ float g_s [B*C*29*29];
__device__ float g_lc[B*C*27*27];
__device__ float g_mc[B*C*25*25];
__device__ float g_sc[B*C*27*27];
__device__ float g_wt[9*C*C];          // transposed search weights [khw][oc][ic], scaled x1024
__device__ float g_scale_t[C], g_bias_t[C];
__device__ float g_scale_s[C], g_bias_s[C];
__device__ float g_scale_1[C], g_bias_1[C];

// ---------------- BN folding ----------------
__global__ void prep_kernel(const float* bt,const float* gt,const float* bet,const float* mt,const float* vt,
                            const float* bs,const float* gs,const float* bes,const float* ms,const float* vs,
                            const float* b1,const float* g1,const float* be1,const float* m1,const float* v1){
    int c = threadIdx.x;
    { float inv = gt[c]*rsqrtf(vt[c]+1e-5f); g_scale_t[c]=inv; g_bias_t[c]=bt[c]*inv + bet[c] - mt[c]*inv; }
    { float inv = gs[c]*rsqrtf(vs[c]+1e-5f); g_scale_s[c]=inv; g_bias_s[c]=bs[c]*inv + bes[c] - ms[c]*inv; }
    { float inv = g1[c]*rsqrtf(v1[c]+1e-5f); g_scale_1[c]=inv; g_bias_1[c]=b1[c]*inv + be1[c] - m1[c]*inv; }
}

// ---------------- weight transpose (+ x1024 scaling for fp16-lo range) --------
__global__ void wt_trans(const float* __restrict__ w){
    int idx = blockIdx.x * 256 + threadIdx.x;
    if (idx < 9*C*C){
        int khw = idx % 9;
        int rest = idx / 9;          // oc*256 + ic
        int ic = rest & 255;
        int oc = rest >> 8;
        g_wt[khw*C*C + oc*C + ic] = w[idx] * 1024.0f;
    }
}

// ---------------- merged template conv 3x3 + BN + ReLU, f32x2 ----------------
template<int W, int NP>
__device__ __forceinline__ void row3(const float* ip, const u64* wdA, const u64* wdB,
                                     u64* aA, u64* aB){
#pragma unroll
    for (int kh = 0; kh < 3; kh++){
        float rv[2*NP+2];
#pragma unroll
        for (int j = 0; j < 2*NP+2; j++) rv[j] = ip[kh*W + j];
        u64 pe[NP+1], po[NP];
#pragma unroll
        for (int p = 0; p <= NP; p++) pe[p] = pack2(rv[2*p], rv[2*p+1]);
#pragma unroll
        for (int p = 0; p < NP; p++) po[p] = pack2(rv[2*p+1], rv[2*p+2]);
#pragma unroll
        for (int p = 0; p < NP; p++){
            fma2(aA[p], pe[p],   wdA[kh*3+0]);
            fma2(aA[p], po[p],   wdA[kh*3+1]);
            fma2(aA[p], pe[p+1], wdA[kh*3+2]);
            fma2(aB[p], pe[p],   wdB[kh*3+0]);
            fma2(aB[p], po[p],   wdB[kh*3+1]);
            fma2(aB[p], pe[p+1], wdB[kh*3+2]);
        }
    }
}

template<int OH, int NP>
__device__ __forceinline__ void tmpl_store(float* out, int b, int oc0, int row,
                                           const u64* aA, const u64* aB){
    float scA = g_scale_t[oc0],   biA = g_bias_t[oc0];
    float scB = g_scale_t[oc0+1], biB = g_bias_t[oc0+1];
    float* pA = out + (((size_t)b*C + oc0  )*OH + row)*OH;
    float* pB = out + (((size_t)b*C + oc0+1)*OH + row)*OH;
#pragma unroll
    for (int p = 0; p < NP; p++){
        float2 fa = unpk(aA[p]), fb = unpk(aB[p]);
        int col = 2*p;
        if (col < OH){
            float va = fmaf(scA, fa.x, biA); pA[col] = va > 0.f ? va : 0.f;
            float vb = fmaf(scB, fb.x, biB); pB[col] = vb > 0.f ? vb : 0.f;
        }
        if (col+1 < OH){
            float va = fmaf(scA, fa.y, biA); pA[col+1] = va > 0.f ? va : 0.f;
            float vb = fmaf(scB, fb.y, biB); pB[col+1] = vb > 0.f ? vb : 0.f;
        }
    }
}

__global__ void __launch_bounds__(512) tmpl_all(const float* __restrict__ lin,
                                                const float* __restrict__ min_,
                                                const float* __restrict__ sin_,
                                                const float* __restrict__ w,
                                                float* lo, float* mo, float* so){
    __shared__ __align__(16) float s_in[16*155 + 4];
    __shared__ __align__(16) float s_w[144*66];
    int tid = threadIdx.x;
    int ocp = tid & 31, slot = tid >> 5;
    int b = blockIdx.x, ocbase = blockIdx.y * 64;
    int oc0 = ocbase + ocp*2;

    u64 aA[4] = {0,0,0,0}, aB[4] = {0,0,0,0};

    for (int ic0 = 0; ic0 < C; ic0 += 16){
        __syncthreads();
#pragma unroll 1
        for (int idx = tid; idx < 16*155; idx += 512){
            int ic = idx / 155, r = idx % 155;
            size_t cb = (size_t)b*C + ic0 + ic;
            float v;
            if (r < 81)       v = lin [cb*81 + r];
            else if (r < 130) v = min_[cb*49 + (r-81)];
            else              v = sin_[cb*25 + (r-130)];
            s_in[ic*155 + r] = v;
        }
#pragma unroll 1
        for (int idx = tid; idx < 64*144; idx += 512){
            int oc = idx / 144, r = idx % 144;
            s_w[r*66 + oc] = w[(size_t)(ocbase+oc)*2304 + (size_t)ic0*9 + r];
        }
        __syncthreads();

        if (slot < 7){
            int row = slot;
#pragma unroll 1
            for (int ic = 0; ic < 16; ic++){
                u64 wdA[9], wdB[9];
#pragma unroll
                for (int k = 0; k < 9; k++){
                    u64 pr = *(const u64*)&s_w[(ic*9+k)*66 + ocp*2];
                    float2 f = unpk(pr);
                    wdA[k] = dup2(f.x); wdB[k] = dup2(f.y);
                }
                row3<9,4>(s_in + ic*155 + row*9, wdA, wdB, aA, aB);
            }
        } else if (slot < 12){
            int row = slot - 7;
#pragma unroll 1
            for (int ic = 0; ic < 16; ic++){
                u64 wdA[9], wdB[9];
#pragma unroll
                for (int k = 0; k < 9; k++){
                    u64 pr = *(const u64*)&s_w[(ic*9+k)*66 + ocp*2];
                    float2 f = unpk(pr);
                    wdA[k] = dup2(f.x); wdB[k] = dup2(f.y);
                }
                row3<7,3>(s_in + ic*155 + 81 + row*7, wdA, wdB, aA, aB);
            }
        } else if (slot < 15){
            int row = slot - 12;
#pragma unroll 1
            for (int ic = 0; ic < 16; ic++){
                u64 wdA[9], wdB[9];
#pragma unroll
                for (int k = 0; k < 9; k++){
                    u64 pr = *(const u64*)&s_w[(ic*9+k)*66 + ocp*2];
                    float2 f = unpk(pr);
                    wdA[k] = dup2(f.x); wdB[k] = dup2(f.y);
                }
                row3<5,2>(s_in + ic*155 + 130 + row*5, wdA, wdB, aA, aB);
            }
        }
    }

    if (slot < 7)       tmpl_store<7,4>(lo, b, oc0, slot,      aA, aB);
    else if (slot < 12) tmpl_store<5,3>(mo, b, oc0, slot - 7,  aA, aB);
    else if (slot < 15) tmpl_store<3,2>(so, b, oc0, slot - 12, aA, aB);
}

// ---------------- search conv via 3-term fp16-split mma.m16n8k16 ----------------
// Double-buffered B staging: one __syncthreads per khw, staging overlapped with MMA.
#define SA_ROWS 248
#define SA_STRIDE 20
#define SA_N (SA_ROWS*SA_STRIDE)
#define SB_STRIDE 20
#define SB_BUF (64*SB_STRIDE)
#define CSM_BYTES ((2*SA_N + 4*SB_BUF) * 4)

#define MMA16(acc, a0,a1,a2,a3, b0,b1) \
    asm volatile( \
        "mma.sync.aligned.m16n8k16.row.col.f32.f16.f16.f32 " \
        "{%0,%1,%2,%3}, {%4,%5,%6,%7}, {%8,%9}, {%0,%1,%2,%3};" \
        : "+f"((acc)[0]), "+f"((acc)[1]), "+f"((acc)[2]), "+f"((acc)[3]) \
        : "r"(a0), "r"(a1), "r"(a2), "r"(a3), "r"(b0), "r"(b1))

__device__ __forceinline__ void stage_b(u32* dst_h, u32* dst_l,
                                        const float* __restrict__ wp, int tid){
#pragma unroll
    for (int rep = 0; rep < 4; rep++){
        int idx = tid + rep*256;
        int oc = idx >> 4, icp = idx & 15;
        float2 vv = *(const float2*)&wp[oc*C + icp*2];
        __half h0 = __float2half_rn(vv.x), h1 = __float2half_rn(vv.y);
        float r0 = vv.x - __half2float(h0), r1 = vv.y - __half2float(h1);
        dst_h[oc*SB_STRIDE + icp] = h2pack(h0, h1);
        dst_l[oc*SB_STRIDE + icp] = h2pack(__float2half_rn(r0), __float2half_rn(r1));
    }
}

__global__ void __launch_bounds__(256) conv_search_mma(const float* __restrict__ in){
    extern __shared__ u32 smem_dyn[];
    u32* sa_h = smem_dyn;
    u32* sa_l = sa_h + SA_N;
    u32* sb_h[2] = { sa_l + SA_N, sa_l + SA_N + SB_BUF };
    u32* sb_l[2] = { sb_h[1] + SB_BUF, sb_h[1] + 2*SB_BUF };

    int tid = threadIdx.x;
    int lane = tid & 31, wid = tid >> 5;
    int g = lane >> 2, t = lane & 3;
    int wm = wid & 3, wn = wid >> 2;
    int b = blockIdx.x;
    int pstart = blockIdx.y * 128;
    int ocb0 = blockIdx.z * 64;
    int r_first = pstart / 29;

    int rc0[2][2], pxv[2][2];
    bool pvalid[2][2];
#pragma unroll
    for (int mf = 0; mf < 2; mf++)
#pragma unroll
        for (int h = 0; h < 2; h++){
            int px = pstart + wm*32 + mf*16 + g + h*8;
            pvalid[mf][h] = (px < 841);
            int pxc = px < 841 ? px : 840;
            pxv[mf][h] = pxc;
            int r = pxc / 29, c = pxc - r*29;
            rc0[mf][h] = (r - r_first)*31 + c;
        }

    float acc[2][4][4];
#pragma unroll
    for (int mf = 0; mf < 2; mf++)
#pragma unroll
        for (int nf = 0; nf < 4; nf++)
#pragma unroll
            for (int i = 0; i < 4; i++) acc[mf][nf][i] = 0.f;

    const float* inb = in + (size_t)b * C * 961;

    for (int ic0 = 0; ic0 < C; ic0 += 32){
        // stage A (hi/lo fp16x2, 16 u32 per row = 32 ic)
#pragma unroll 1
        for (int icp = 0; icp < 16; icp++){
            int rc = tid;
            if (rc < SA_ROWS){
                int gidx = r_first*31 + rc;
                int ic = ic0 + icp*2;
                float v0 = 0.f, v1 = 0.f;
                if (gidx < 961){
                    v0 = inb[ic*961 + gidx];
                    v1 = inb[(ic+1)*961 + gidx];
                }
                __half h0 = __float2half_rn(v0), h1 = __float2half_rn(v1);
                float r0 = v0 - __half2float(h0), r1 = v1 - __half2float(h1);
                sa_h[rc*SA_STRIDE + icp] = h2pack(h0, h1);
                sa_l[rc*SA_STRIDE + icp] = h2pack(__float2half_rn(r0), __float2half_rn(r1));
            }
        }
        // stage B for khw=0
        stage_b(sb_h[0], sb_l[0], g_wt + (size_t)ocb0*C + ic0, tid);
        __syncthreads();

#pragma unroll 1
        for (int khw = 0; khw < 9; khw++){
            int cur = khw & 1, nxt = cur ^ 1;
            if (khw < 8)
                stage_b(sb_h[nxt], sb_l[nxt],
                        g_wt + (size_t)(khw+1)*C*C + (size_t)ocb0*C + ic0, tid);
            int kh = khw / 3, kw = khw - kh*3;
            int sh = kh*31 + kw;
            u32* bh = sb_h[cur];
            u32* bl = sb_l[cur];
#pragma unroll
            for (int ks = 0; ks < 2; ks++){
                int k0 = ks * 8;
                u32 bh0[4], bh1[4], bl0[4], bl1[4];
#pragma unroll
                for (int nf = 0; nf < 4; nf++){
                    int ocl = wn*32 + nf*8 + g;
                    bh0[nf] = bh[ocl*SB_STRIDE + k0 + t];
                    bh1[nf] = bh[ocl*SB_STRIDE + k0 + t + 4];
                    bl0[nf] = bl[ocl*SB_STRIDE + k0 + t];
                    bl1[nf] = bl[ocl*SB_STRIDE + k0 + t + 4];
                }
#pragma unroll
                for (int mf = 0; mf < 2; mf++){
                    int i0 = (rc0[mf][0] + sh)*SA_STRIDE + k0 + t;
                    int i1 = (rc0[mf][1] + sh)*SA_STRIDE + k0 + t;
                    u32 ah0 = sa_h[i0], ah1 = sa_h[i1];
                    u32 ah2 = sa_h[i0+4], ah3 = sa_h[i1+4];
                    u32 al0 = sa_l[i0], al1 = sa_l[i1];
                    u32 al2 = sa_l[i0+4], al3 = sa_l[i1+4];
#pragma unroll
                    for (int nf = 0; nf < 4; nf++){
                        MMA16(acc[mf][nf], ah0, ah1, ah2, ah3, bh0[nf], bh1[nf]);
                        MMA16(acc[mf][nf], ah0, ah1, ah2, ah3, bl0[nf], bl1[nf]);
                        MMA16(acc[mf][nf], al0, al1, al2, al3, bh0[nf], bh1[nf]);
                    }
                }
            }
            __syncthreads();
        }
    }

    // epilogue: BN + ReLU (undo x1024 weight scaling), scatter to g_s[b][oc][px]
    const float inv1024 = 0.0009765625f;
#pragma unroll
    for (int nf = 0; nf < 4; nf++){
        int oc0 = ocb0 + wn*32 + nf*8 + 2*t;
        int oc1 = oc0 + 1;
        float sc0 = g_scale_s[oc0] * inv1024, bi0 = g_bias_s[oc0];
        float sc1 = g_scale_s[oc1] * inv1024, bi1 = g_bias_s[oc1];
#pragma unroll
        for (int mf = 0; mf < 2; mf++){
            if (pvalid[mf][0]){
                float v0 = fmaf(sc0, acc[mf][nf][0], bi0);
                float v1 = fmaf(sc1, acc[mf][nf][1], bi1);
                g_s[((size_t)b*C + oc0)*841 + pxv[mf][0]] = v0 > 0.f ? v0 : 0.f;
                g_s[((size_t)b*C + oc1)*841 + pxv[mf][0]] = v1 > 0.f ? v1 : 0.f;
            }
            if (pvalid[mf][1]){
                float v2 = fmaf(sc0, acc[mf][nf][2], bi0);
                float v3 = fmaf(sc1, acc[mf][nf][3], bi1);
                g_s[((size_t)b*C + oc0)*841 + pxv[mf][1]] = v2 > 0.f ? v2 : 0.f;
                g_s[((size_t)b*C + oc1)*841 + pxv[mf][1]] = v3 > 0.f ? v3 : 0.f;
            }
        }
    }
}

// ---------------- corr v2: warp = channel, lane = output row, f32x2 --------------
template<int TS, int PAD, int OS>
__global__ void __launch_bounds__(256) corr_v2(const float* __restrict__ t,
                                               float* __restrict__ out){
    constexpr int R = OS + TS - 1;
    constexpr int STRIDE = 35;
    constexpr int NPAIR = (OS + 1) / 2;
    constexpr int VW = 2*NPAIR + TS - 1;
    constexpr int NPE = VW / 2;
    __shared__ float s_pad[8 * R * STRIDE];
    __shared__ float s_t[8 * TS * TS];
    int tid = threadIdx.x;
    int wrp = tid >> 5, lane = tid & 31;
    int b = blockIdx.x;
    int c0 = blockIdx.y * 8;

#pragma unroll 1
    for (int idx = tid; idx < 8 * R * STRIDE; idx += 256) s_pad[idx] = 0.f;
    __syncthreads();
    const float* sb = g_s + ((size_t)b*C + c0) * 841;
#pragma unroll 1
    for (int idx = tid; idx < 8 * 841; idx += 256){
        int ch = idx / 841, rem = idx - ch*841;
        int row = rem / 29, col = rem - row*29;
        s_pad[ch*R*STRIDE + (row + PAD)*STRIDE + col + PAD] = sb[ch*841 + rem];
    }
    const float* tb = t + ((size_t)b*C + c0) * TS * TS;
#pragma unroll 1
    for (int idx = tid; idx < 8 * TS * TS; idx += 256) s_t[idx] = tb[idx];
    __syncthreads();

    if (lane < OS){
        const float* sp = s_pad + wrp*R*STRIDE + lane*STRIDE;
        const float* tp = s_t + wrp*TS*TS;
        u64 a[NPAIR];
#pragma unroll
        for (int p = 0; p < NPAIR; p++) a[p] = 0ull;
#pragma unroll
        for (int trow = 0; trow < TS; trow++){
            u64 wd[TS];
#pragma unroll
            for (int j = 0; j < TS; j++) wd[j] = dup2(tp[trow*TS + j]);
            float v[VW];
#pragma unroll
            for (int k = 0; k < VW; k++) v[k] = sp[trow*STRIDE + k];
            u64 pe[NPE], po[NPE-1];
#pragma unroll
            for (int k = 0; k < NPE; k++) pe[k] = pack2(v[2*k], v[2*k+1]);
#pragma unroll
            for (int k = 0; k < NPE-1; k++) po[k] = pack2(v[2*k+1], v[2*k+2]);
#pragma unroll
            for (int j = 0; j < TS; j++){
                if (j & 1){
#pragma unroll
                    for (int p = 0; p < NPAIR; p++) fma2(a[p], po[p + (j>>1)], wd[j]);
                } else {
#pragma unroll
                    for (int p = 0; p < NPAIR; p++) fma2(a[p], pe[p + (j>>1)], wd[j]);
                }
            }
        }
        float* op = out + (((size_t)b*C + c0 + wrp)*OS + lane)*OS;
#pragma unroll
        for (int p = 0; p < NPAIR; p++){
            float2 f = unpk(a[p]);
            op[2*p] = f.x;
            if (2*p + 1 < OS) op[2*p + 1] = f.y;
        }
    }
}

// ---------------- head v2: thread = 4 n x 16 px --------------------------------
__global__ void __launch_bounds__(256) head_kernel(const float* __restrict__ x, int HW,
                                                   const float* __restrict__ w1,
                                                   const float* __restrict__ w2,
                                                   const float* __restrict__ b2,
                                                   float* __restrict__ out){
    __shared__ __align__(16) float s_w[32 * 260];
    __shared__ __align__(16) float s_x[32 * 64];
    __shared__ float s_red[8][16];
    int tid = threadIdx.x;
    int nq = tid & 63;
    int pg = tid >> 6;
    int n0 = nq * 4;
    int b = blockIdx.y;
    int p0 = blockIdx.x * 64;
    const float* xb = x + (size_t)b * C * HW;

    u64 acc[4][8];
#pragma unroll
    for (int i = 0; i < 4; i++)
#pragma unroll
        for (int p = 0; p < 8; p++) acc[i][p] = 0ull;

    for (int k0 = 0; k0 < C; k0 += 32){
        __syncthreads();
#pragma unroll 1
        for (int idx = tid; idx < 8192; idx += 256){
            int kk = idx & 31, n = idx >> 5;
            s_w[kk*260 + n] = w1[n*C + k0 + kk];
        }
#pragma unroll 1
        for (int idx = tid; idx < 2048; idx += 256){
            int p = idx & 63, kk = idx >> 6;
            int gp = p0 + p;
            s_x[kk*64 + p] = (gp < HW) ? xb[(k0+kk)*HW + gp] : 0.f;
        }
        __syncthreads();
#pragma unroll 4
        for (int kk = 0; kk < 32; kk++){
            float4 wf = *(const float4*)&s_w[kk*260 + n0];
            u64 w0 = dup2(wf.x), w1d = dup2(wf.y), w2d = dup2(wf.z), w3d = dup2(wf.w);
            const u64* xp = (const u64*)(s_x + kk*64) + pg*8;
            u64 xv[8];
#pragma unroll
            for (int p = 0; p < 8; p++) xv[p] = xp[p];
#pragma unroll
            for (int p = 0; p < 8; p++){
                fma2(acc[0][p], xv[p], w0);
                fma2(acc[1][p], xv[p], w1d);
                fma2(acc[2][p], xv[p], w2d);
                fma2(acc[3][p], xv[p], w3d);
            }
        }
    }

    u64 psum[8];
#pragma unroll
    for (int p = 0; p < 8; p++) psum[p] = 0ull;
#pragma unroll
    for (int i = 0; i < 4; i++){
        float sc = g_scale_1[n0+i], bi = g_bias_1[n0+i], wv = w2[n0+i];
#pragma unroll
        for (int p = 0; p < 8; p++){
            float2 f = unpk(acc[i][p]);
            f.x = fmaxf(fmaf(sc, f.x, bi), 0.f) * wv;
            f.y = fmaxf(fmaf(sc, f.y, bi), 0.f) * wv;
            psum[p] = add2(psum[p], pack2(f.x, f.y));
        }
    }
    int lane = tid & 31, wrp = tid >> 5;
#pragma unroll
    for (int p = 0; p < 8; p++){
        u64 v = psum[p];
        v = add2(v, __shfl_xor_sync(0xffffffffu, v, 16));
        v = add2(v, __shfl_xor_sync(0xffffffffu, v, 8));
        v = add2(v, __shfl_xor_sync(0xffffffffu, v, 4));
        v = add2(v, __shfl_xor_sync(0xffffffffu, v, 2));
        v = add2(v, __shfl_xor_sync(0xffffffffu, v, 1));
        psum[p] = v;
    }
    if (lane == 0){
#pragma unroll
        for (int p = 0; p < 8; p++){
            float2 f = unpk(psum[p]);
            s_red[wrp][2*p] = f.x;
            s_red[wrp][2*p+1] = f.y;
        }
    }
    __syncthreads();
    if (tid < 64){
        int pg2 = tid >> 4, j = tid & 15;
        float v = s_red[2*pg2][j] + s_red[2*pg2+1][j];
        int gp = p0 + pg2*16 + j;
        if (gp < HW)
            out[(size_t)b*HW + gp] = 1.f / (1.f + expf(-(v + b2[0])));
    }
}

// ---------------- launch ----------------
extern "C" void kernel_launch(void* const* d_in, const int* in_sizes, int n_in,
                              void* d_out, int out_size){
    const float* large  = (const float*)d_in[0];
    const float* medium = (const float*)d_in[1];
    const float* small  = (const float*)d_in[2];
    const float* search = (const float*)d_in[3];
    const float* wt  = (const float*)d_in[4];
    const float* bt  = (const float*)d_in[5];
    const float* gt  = (const float*)d_in[6];
    const float* bet = (const float*)d_in[7];
    const float* mt  = (const float*)d_in[8];
    const float* vt  = (const float*)d_in[9];
    const float* ws  = (const float*)d_in[10];
    const float* bs  = (const float*)d_in[11];
    const float* gs  = (const float*)d_in[12];
    const float* bes = (const float*)d_in[13];
    const float* ms  = (const float*)d_in[14];
    const float* vs  = (const float*)d_in[15];
    const float* w1  = (const float*)d_in[16];
    const float* b1  = (const float*)d_in[17];
    const float* g1  = (const float*)d_in[18];
    const float* be1 = (const float*)d_in[19];
    const float* m1  = (const float*)d_in[20];
    const float* v1  = (const float*)d_in[21];
    const float* w2  = (const float*)d_in[22];
    const float* b2  = (const float*)d_in[23];
    float* out = (float*)d_out;

    float *lf, *mf, *sf, *lc, *mc, *sc;
    cudaGetSymbolAddress((void**)&lf, g_lf);
    cudaGetSymbolAddress((void**)&mf, g_mf);
    cudaGetSymbolAddress((void**)&sf, g_sf);
    cudaGetSymbolAddress((void**)&lc, g_lc);
    cudaGetSymbolAddress((void**)&mc, g_mc);
    cudaGetSymbolAddress((void**)&sc, g_sc);

    static cudaStream_t st1 = 0, st2 = 0;
    static cudaEvent_t evRoot = 0, evT = 0, evFork = 0, ev1 = 0, ev2 = 0;
    if (!st1){
        cudaStreamCreateWithFlags(&st1, cudaStreamNonBlocking);
        cudaStreamCreateWithFlags(&st2, cudaStreamNonBlocking);
        cudaEventCreateWithFlags(&evRoot, cudaEventDisableTiming);
        cudaEventCreateWithFlags(&evT, cudaEventDisableTiming);
        cudaEventCreateWithFlags(&evFork, cudaEventDisableTiming);
        cudaEventCreateWithFlags(&ev1, cudaEventDisableTiming);
        cudaEventCreateWithFlags(&ev2, cudaEventDisableTiming);
        cudaFuncSetAttribute(conv_search_mma,
                             cudaFuncAttributeMaxDynamicSharedMemorySize, CSM_BYTES);
    }

    prep_kernel<<<1, 256>>>(bt, gt, bet, mt, vt, bs, gs, bes, ms, vs, b1, g1, be1, m1, v1);
    wt_trans<<<(9*C*C + 255)/256, 256>>>(ws);

    // fork: tmpl_all runs on st1 concurrently with conv_search_mma on stream 0
    cudaEventRecord(evRoot, 0);
    cudaStreamWaitEvent(st1, evRoot, 0);
    tmpl_all<<<dim3(64, 4), 512, 0, st1>>>(large, medium, small, wt, lf, mf, sf);
    cudaEventRecord(evT, st1);
    conv_search_mma<<<dim3(64, 7, 4), 256, CSM_BYTES>>>(search);
    cudaStreamWaitEvent(0, evT, 0);

    // fork three independent corr->head chains
    cudaEventRecord(evFork, 0);
    cudaStreamWaitEvent(st1, evFork, 0);
    cudaStreamWaitEvent(st2, evFork, 0);

    corr_v2<7, 2, 27><<<dim3(64, 32), 256>>>(lf, lc);
    head_kernel<<<dim3(12, 64), 256>>>(lc, 729, w1, w2, b2, out);

    corr_v2<5, 0, 25><<<dim3(64, 32), 256, 0, st1>>>(mf, mc);
    head_kernel<<<dim3(10, 64), 256, 0, st1>>>(mc, 625, w1, w2, b2, out + 64*729);
    cudaEventRecord(ev1, st1);

    corr_v2<3, 0, 27><<<dim3(64, 32), 256, 0, st2>>>(sf, sc);
    head_kernel<<<dim3(12, 64), 256, 0, st2>>>(sc, 729, w1, w2, b2, out + 64*729 + 64*625);
    cudaEventRecord(ev2, st2);

    cudaStreamWaitEvent(0, ev1, 0);
    cudaStreamWaitEvent(0, ev2, 0);
}

// round 10
// speedup vs baseline: 1.0691x; 1.0691x over previous
#include <cuda_runtime.h>
#include <cuda_fp16.h>
#include <math.h>

#define B 64
#define C 256

typedef unsigned long long u64;
typedef unsigned int u32;

// ---------------- f32x2 packed-math helpers ----------------
__device__ __forceinline__ u64 pack2(float lo, float hi){
    u64 r; asm("mov.b64 %0, {%1, %2};" : "=l"(r) : "f"(lo), "f"(hi)); return r;
}
__device__ __forceinline__ u64 dup2(float v){
    u64 r; asm("mov.b64 %0, {%1, %1};" : "=l"(r) : "f"(v)); return r;
}
__device__ __forceinline__ void fma2(u64 &d, u64 a, u64 b){
    asm("fma.rn.f32x2 %0, %1, %2, %0;" : "+l"(d) : "l"(a), "l"(b));
}
__device__ __forceinline__ u64 add2(u64 a, u64 b){
    u64 d; asm("add.rn.f32x2 %0, %1, %2;" : "=l"(d) : "l"(a), "l"(b)); return d;
}
__device__ __forceinline__ float2 unpk(u64 v){
    float2 f; asm("mov.b64 {%0, %1}, %2;" : "=f"(f.x), "=f"(f.y) : "l"(v)); return f;
}
__device__ __forceinline__ u32 h2pack(__half a, __half b){
    return ((u32)__half_as_ushort(b) << 16) | (u32)__half_as_ushort(a);
}

// ---------------- scratch ----------------
__device__ float g_lf[B*C*7*7];
__device__ float g_mf[B*C*5*5];
__device__ float g_sf[B*C*3*3];
__device__ float g_s [B*C*29*29];
__device__ float g_lc[B*C*27*27];
__device__ float g_mc[B*C*25*25];
__device__ float g_sc[B*C*27*27];
__device__ float g_wt[9*C*C];          // transposed search weights [khw][oc][ic], scaled x1024
__device__ float g_scale_t[C], g_bias_t[C];
__device__ float g_scale_s[C], g_bias_s[C];
__device__ float g_scale_1[C], g_bias_1[C];

// ---------------- BN folding ----------------
__global__ void prep_kernel(const float* bt,const float* gt,const float* bet,const float* mt,const float* vt,
                            const float* bs,const float* gs,const float* bes,const float* ms,const float* vs,
                            const float* b1,const float* g1,const float* be1,const float* m1,const float* v1){
    int c = threadIdx.x;
    { float inv = gt[c]*rsqrtf(vt[c]+1e-5f); g_scale_t[c]=inv; g_bias_t[c]=bt[c]*inv + bet[c] - mt[c]*inv; }
    { float inv = gs[c]*rsqrtf(vs[c]+1e-5f); g_scale_s[c]=inv; g_bias_s[c]=bs[c]*inv + bes[c] - ms[c]*inv; }
    { float inv = g1[c]*rsqrtf(v1[c]+1e-5f); g_scale_1[c]=inv; g_bias_1[c]=b1[c]*inv + be1[c] - m1[c]*inv; }
}

// ---------------- weight transpose (+ x1024 scaling for fp16-lo range) --------
__global__ void wt_trans(const float* __restrict__ w){
    int idx = blockIdx.x * 256 + threadIdx.x;
    if (idx < 9*C*C){
        int khw = idx % 9;
        int rest = idx / 9;          // oc*256 + ic
        int ic = rest & 255;
        int oc = rest >> 8;
        g_wt[khw*C*C + oc*C + ic] = w[idx] * 1024.0f;
    }
}

// ---------------- merged template conv 3x3 + BN + ReLU, f32x2 ----------------
template<int W, int NP>
__device__ __forceinline__ void row3(const float* ip, const u64* wdA, const u64* wdB,
                                     u64* aA, u64* aB){
#pragma unroll
    for (int kh = 0; kh < 3; kh++){
        float rv[2*NP+2];
#pragma unroll
        for (int j = 0; j < 2*NP+2; j++) rv[j] = ip[kh*W + j];
        u64 pe[NP+1], po[NP];
#pragma unroll
        for (int p = 0; p <= NP; p++) pe[p] = pack2(rv[2*p], rv[2*p+1]);
#pragma unroll
        for (int p = 0; p < NP; p++) po[p] = pack2(rv[2*p+1], rv[2*p+2]);
#pragma unroll
        for (int p = 0; p < NP; p++){
            fma2(aA[p], pe[p],   wdA[kh*3+0]);
            fma2(aA[p], po[p],   wdA[kh*3+1]);
            fma2(aA[p], pe[p+1], wdA[kh*3+2]);
            fma2(aB[p], pe[p],   wdB[kh*3+0]);
            fma2(aB[p], po[p],   wdB[kh*3+1]);
            fma2(aB[p], pe[p+1], wdB[kh*3+2]);
        }
    }
}

template<int OH, int NP>
__device__ __forceinline__ void tmpl_store(float* out, int b, int oc0, int row,
                                           const u64* aA, const u64* aB){
    float scA = g_scale_t[oc0],   biA = g_bias_t[oc0];
    float scB = g_scale_t[oc0+1], biB = g_bias_t[oc0+1];
    float* pA = out + (((size_t)b*C + oc0  )*OH + row)*OH;
    float* pB = out + (((size_t)b*C + oc0+1)*OH + row)*OH;
#pragma unroll
    for (int p = 0; p < NP; p++){
        float2 fa = unpk(aA[p]), fb = unpk(aB[p]);
        int col = 2*p;
        if (col < OH){
            float va = fmaf(scA, fa.x, biA); pA[col] = va > 0.f ? va : 0.f;
            float vb = fmaf(scB, fb.x, biB); pB[col] = vb > 0.f ? vb : 0.f;
        }
        if (col+1 < OH){
            float va = fmaf(scA, fa.y, biA); pA[col+1] = va > 0.f ? va : 0.f;
            float vb = fmaf(scB, fb.y, biB); pB[col+1] = vb > 0.f ? vb : 0.f;
        }
    }
}

__global__ void __launch_bounds__(512) tmpl_all(const float* __restrict__ lin,
                                                const float* __restrict__ min_,
                                                const float* __restrict__ sin_,
                                                const float* __restrict__ w,
                                                float* lo, float* mo, float* so){
    __shared__ __align__(16) float s_in[16*155 + 4];
    __shared__ __align__(16) float s_w[144*66];
    int tid = threadIdx.x;
    int ocp = tid & 31, slot = tid >> 5;
    int b = blockIdx.x, ocbase = blockIdx.y * 64;
    int oc0 = ocbase + ocp*2;

    u64 aA[4] = {0,0,0,0}, aB[4] = {0,0,0,0};

    for (int ic0 = 0; ic0 < C; ic0 += 16){
        __syncthreads();
#pragma unroll 1
        for (int idx = tid; idx < 16*155; idx += 512){
            int ic = idx / 155, r = idx % 155;
            size_t cb = (size_t)b*C + ic0 + ic;
            float v;
            if (r < 81)       v = lin [cb*81 + r];
            else if (r < 130) v = min_[cb*49 + (r-81)];
            else              v = sin_[cb*25 + (r-130)];
            s_in[ic*155 + r] = v;
        }
#pragma unroll 1
        for (int idx = tid; idx < 64*144; idx += 512){
            int oc = idx / 144, r = idx % 144;
            s_w[r*66 + oc] = w[(size_t)(ocbase+oc)*2304 + (size_t)ic0*9 + r];
        }
        __syncthreads();

        if (slot < 7){
            int row = slot;
#pragma unroll 1
            for (int ic = 0; ic < 16; ic++){
                u64 wdA[9], wdB[9];
#pragma unroll
                for (int k = 0; k < 9; k++){
                    u64 pr = *(const u64*)&s_w[(ic*9+k)*66 + ocp*2];
                    float2 f = unpk(pr);
                    wdA[k] = dup2(f.x); wdB[k] = dup2(f.y);
                }
                row3<9,4>(s_in + ic*155 + row*9, wdA, wdB, aA, aB);
            }
        } else if (slot < 12){
            int row = slot - 7;
#pragma unroll 1
            for (int ic = 0; ic < 16; ic++){
                u64 wdA[9], wdB[9];
#pragma unroll
                for (int k = 0; k < 9; k++){
                    u64 pr = *(const u64*)&s_w[(ic*9+k)*66 + ocp*2];
                    float2 f = unpk(pr);
                    wdA[k] = dup2(f.x); wdB[k] = dup2(f.y);
                }
                row3<7,3>(s_in + ic*155 + 81 + row*7, wdA, wdB, aA, aB);
            }
        } else if (slot < 15){
            int row = slot - 12;
#pragma unroll 1
            for (int ic = 0; ic < 16; ic++){
                u64 wdA[9], wdB[9];
#pragma unroll
                for (int k = 0; k < 9; k++){
                    u64 pr = *(const u64*)&s_w[(ic*9+k)*66 + ocp*2];
                    float2 f = unpk(pr);
                    wdA[k] = dup2(f.x); wdB[k] = dup2(f.y);
                }
                row3<5,2>(s_in + ic*155 + 130 + row*5, wdA, wdB, aA, aB);
            }
        }
    }

    if (slot < 7)       tmpl_store<7,4>(lo, b, oc0, slot,      aA, aB);
    else if (slot < 12) tmpl_store<5,3>(mo, b, oc0, slot - 7,  aA, aB);
    else if (slot < 15) tmpl_store<3,2>(so, b, oc0, slot - 12, aA, aB);
}

// ---------------- search conv via 3-term fp16-split mma.m16n8k16 (R7 version) ----
#define SA_ROWS 248
#define SA_STRIDE 20
#define SA_N (SA_ROWS*SA_STRIDE)
#define SB_STRIDE 20
#define SB_N (64*SB_STRIDE)
#define CSM_BYTES ((2*SA_N + 2*SB_N) * 4)

#define MMA16(acc, a0,a1,a2,a3, b0,b1) \
    asm volatile( \
        "mma.sync.aligned.m16n8k16.row.col.f32.f16.f16.f32 " \
        "{%0,%1,%2,%3}, {%4,%5,%6,%7}, {%8,%9}, {%0,%1,%2,%3};" \
        : "+f"((acc)[0]), "+f"((acc)[1]), "+f"((acc)[2]), "+f"((acc)[3]) \
        : "r"(a0), "r"(a1), "r"(a2), "r"(a3), "r"(b0), "r"(b1))

__global__ void __launch_bounds__(256) conv_search_mma(const float* __restrict__ in){
    extern __shared__ u32 smem_dyn[];
    u32* sa_h = smem_dyn;
    u32* sa_l = sa_h + SA_N;
    u32* sb_h = sa_l + SA_N;
    u32* sb_l = sb_h + SB_N;

    int tid = threadIdx.x;
    int lane = tid & 31, wid = tid >> 5;
    int g = lane >> 2, t = lane & 3;
    int wm = wid & 3, wn = wid >> 2;
    int b = blockIdx.x;
    int pstart = blockIdx.y * 128;
    int ocb0 = blockIdx.z * 64;
    int r_first = pstart / 29;

    int rc0[2][2], pxv[2][2];
    bool pvalid[2][2];
#pragma unroll
    for (int mf = 0; mf < 2; mf++)
#pragma unroll
        for (int h = 0; h < 2; h++){
            int px = pstart + wm*32 + mf*16 + g + h*8;
            pvalid[mf][h] = (px < 841);
            int pxc = px < 841 ? px : 840;
            pxv[mf][h] = pxc;
            int r = pxc / 29, c = pxc - r*29;
            rc0[mf][h] = (r - r_first)*31 + c;
        }

    float acc[2][4][4];
#pragma unroll
    for (int mf = 0; mf < 2; mf++)
#pragma unroll
        for (int nf = 0; nf < 4; nf++)
#pragma unroll
            for (int i = 0; i < 4; i++) acc[mf][nf][i] = 0.f;

    const float* inb = in + (size_t)b * C * 961;

    for (int ic0 = 0; ic0 < C; ic0 += 32){
        __syncthreads();
        // stage A (hi/lo fp16x2, 16 u32 per row = 32 ic)
#pragma unroll 1
        for (int icp = 0; icp < 16; icp++){
            int rc = tid;
            if (rc < SA_ROWS){
                int gidx = r_first*31 + rc;
                int ic = ic0 + icp*2;
                float v0 = 0.f, v1 = 0.f;
                if (gidx < 961){
                    v0 = inb[ic*961 + gidx];
                    v1 = inb[(ic+1)*961 + gidx];
                }
                __half h0 = __float2half_rn(v0), h1 = __float2half_rn(v1);
                float r0 = v0 - __half2float(h0), r1 = v1 - __half2float(h1);
                sa_h[rc*SA_STRIDE + icp] = h2pack(h0, h1);
                sa_l[rc*SA_STRIDE + icp] = h2pack(__float2half_rn(r0), __float2half_rn(r1));
            }
        }
#pragma unroll 1
        for (int khw = 0; khw < 9; khw++){
            __syncthreads();
            const float* wp = g_wt + (size_t)khw*C*C + (size_t)ocb0*C + ic0;
#pragma unroll 1
            for (int idx = tid; idx < 64*16; idx += 256){
                int oc = idx >> 4, icp = idx & 15;
                float2 vv = *(const float2*)&wp[oc*C + icp*2];
                __half h0 = __float2half_rn(vv.x), h1 = __float2half_rn(vv.y);
                float r0 = vv.x - __half2float(h0), r1 = vv.y - __half2float(h1);
                sb_h[oc*SB_STRIDE + icp] = h2pack(h0, h1);
                sb_l[oc*SB_STRIDE + icp] = h2pack(__float2half_rn(r0), __float2half_rn(r1));
            }
            __syncthreads();
            int kh = khw / 3, kw = khw - kh*3;
            int sh = kh*31 + kw;
#pragma unroll
            for (int ks = 0; ks < 2; ks++){
                int k0 = ks * 8;
                u32 bh0[4], bh1[4], bl0[4], bl1[4];
#pragma unroll
                for (int nf = 0; nf < 4; nf++){
                    int ocl = wn*32 + nf*8 + g;
                    bh0[nf] = sb_h[ocl*SB_STRIDE + k0 + t];
                    bh1[nf] = sb_h[ocl*SB_STRIDE + k0 + t + 4];
                    bl0[nf] = sb_l[ocl*SB_STRIDE + k0 + t];
                    bl1[nf] = sb_l[ocl*SB_STRIDE + k0 + t + 4];
                }
#pragma unroll
                for (int mf = 0; mf < 2; mf++){
                    int i0 = (rc0[mf][0] + sh)*SA_STRIDE + k0 + t;
                    int i1 = (rc0[mf][1] + sh)*SA_STRIDE + k0 + t;
                    u32 ah0 = sa_h[i0], ah1 = sa_h[i1];
                    u32 ah2 = sa_h[i0+4], ah3 = sa_h[i1+4];
                    u32 al0 = sa_l[i0], al1 = sa_l[i1];
                    u32 al2 = sa_l[i0+4], al3 = sa_l[i1+4];
#pragma unroll
                    for (int nf = 0; nf < 4; nf++){
                        MMA16(acc[mf][nf], ah0, ah1, ah2, ah3, bh0[nf], bh1[nf]);
                        MMA16(acc[mf][nf], ah0, ah1, ah2, ah3, bl0[nf], bl1[nf]);
                        MMA16(acc[mf][nf], al0, al1, al2, al3, bh0[nf], bh1[nf]);
                    }
                }
            }
        }
    }

    const float inv1024 = 0.0009765625f;
#pragma unroll
    for (int nf = 0; nf < 4; nf++){
        int oc0 = ocb0 + wn*32 + nf*8 + 2*t;
        int oc1 = oc0 + 1;
        float sc0 = g_scale_s[oc0] * inv1024, bi0 = g_bias_s[oc0];
        float sc1 = g_scale_s[oc1] * inv1024, bi1 = g_bias_s[oc1];
#pragma unroll
        for (int mf = 0; mf < 2; mf++){
            if (pvalid[mf][0]){
                float v0 = fmaf(sc0, acc[mf][nf][0], bi0);
                float v1 = fmaf(sc1, acc[mf][nf][1], bi1);
                g_s[((size_t)b*C + oc0)*841 + pxv[mf][0]] = v0 > 0.f ? v0 : 0.f;
                g_s[((size_t)b*C + oc1)*841 + pxv[mf][0]] = v1 > 0.f ? v1 : 0.f;
            }
            if (pvalid[mf][1]){
                float v2 = fmaf(sc0, acc[mf][nf][2], bi0);
                float v3 = fmaf(sc1, acc[mf][nf][3], bi1);
                g_s[((size_t)b*C + oc0)*841 + pxv[mf][1]] = v2 > 0.f ? v2 : 0.f;
                g_s[((size_t)b*C + oc1)*841 + pxv[mf][1]] = v3 > 0.f ? v3 : 0.f;
            }
        }
    }
}

// ---------------- corr v2: warp = channel, lane = output row, f32x2 --------------
template<int TS, int PAD, int OS>
__global__ void __launch_bounds__(256) corr_v2(const float* __restrict__ t,
                                               float* __restrict__ out){
    constexpr int R = OS + TS - 1;
    constexpr int STRIDE = 35;
    constexpr int NPAIR = (OS + 1) / 2;
    constexpr int VW = 2*NPAIR + TS - 1;
    constexpr int NPE = VW / 2;
    __shared__ float s_pad[8 * R * STRIDE];
    __shared__ float s_t[8 * TS * TS];
    int tid = threadIdx.x;
    int wrp = tid >> 5, lane = tid & 31;
    int b = blockIdx.x;
    int c0 = blockIdx.y * 8;

#pragma unroll 1
    for (int idx = tid; idx < 8 * R * STRIDE; idx += 256) s_pad[idx] = 0.f;
    __syncthreads();
    const float* sb = g_s + ((size_t)b*C + c0) * 841;
#pragma unroll 1
    for (int idx = tid; idx < 8 * 841; idx += 256){
        int ch = idx / 841, rem = idx - ch*841;
        int row = rem / 29, col = rem - row*29;
        s_pad[ch*R*STRIDE + (row + PAD)*STRIDE + col + PAD] = sb[ch*841 + rem];
    }
    const float* tb = t + ((size_t)b*C + c0) * TS * TS;
#pragma unroll 1
    for (int idx = tid; idx < 8 * TS * TS; idx += 256) s_t[idx] = tb[idx];
    __syncthreads();

    if (lane < OS){
        const float* sp = s_pad + wrp*R*STRIDE + lane*STRIDE;
        const float* tp = s_t + wrp*TS*TS;
        u64 a[NPAIR];
#pragma unroll
        for (int p = 0; p < NPAIR; p++) a[p] = 0ull;
#pragma unroll
        for (int trow = 0; trow < TS; trow++){
            u64 wd[TS];
#pragma unroll
            for (int j = 0; j < TS; j++) wd[j] = dup2(tp[trow*TS + j]);
            float v[VW];
#pragma unroll
            for (int k = 0; k < VW; k++) v[k] = sp[trow*STRIDE + k];
            u64 pe[NPE], po[NPE-1];
#pragma unroll
            for (int k = 0; k < NPE; k++) pe[k] = pack2(v[2*k], v[2*k+1]);
#pragma unroll
            for (int k = 0; k < NPE-1; k++) po[k] = pack2(v[2*k+1], v[2*k+2]);
#pragma unroll
            for (int j = 0; j < TS; j++){
                if (j & 1){
#pragma unroll
                    for (int p = 0; p < NPAIR; p++) fma2(a[p], po[p + (j>>1)], wd[j]);
                } else {
#pragma unroll
                    for (int p = 0; p < NPAIR; p++) fma2(a[p], pe[p + (j>>1)], wd[j]);
                }
            }
        }
        float* op = out + (((size_t)b*C + c0 + wrp)*OS + lane)*OS;
#pragma unroll
        for (int p = 0; p < NPAIR; p++){
            float2 f = unpk(a[p]);
            op[2*p] = f.x;
            if (2*p + 1 < OS) op[2*p + 1] = f.y;
        }
    }
}

// ---------------- head v2: thread = 4 n x 16 px --------------------------------
__global__ void __launch_bounds__(256) head_kernel(const float* __restrict__ x, int HW,
                                                   const float* __restrict__ w1,
                                                   const float* __restrict__ w2,
                                                   const float* __restrict__ b2,
                                                   float* __restrict__ out){
    __shared__ __align__(16) float s_w[32 * 260];
    __shared__ __align__(16) float s_x[32 * 64];
    __shared__ float s_red[8][16];
    int tid = threadIdx.x;
    int nq = tid & 63;
    int pg = tid >> 6;
    int n0 = nq * 4;
    int b = blockIdx.y;
    int p0 = blockIdx.x * 64;
    const float* xb = x + (size_t)b * C * HW;

    u64 acc[4][8];
#pragma unroll
    for (int i = 0; i < 4; i++)
#pragma unroll
        for (int p = 0; p < 8; p++) acc[i][p] = 0ull;

    for (int k0 = 0; k0 < C; k0 += 32){
        __syncthreads();
#pragma unroll 1
        for (int idx = tid; idx < 8192; idx += 256){
            int kk = idx & 31, n = idx >> 5;
            s_w[kk*260 + n] = w1[n*C + k0 + kk];
        }
#pragma unroll 1
        for (int idx = tid; idx < 2048; idx += 256){
            int p = idx & 63, kk = idx >> 6;
            int gp = p0 + p;
            s_x[kk*64 + p] = (gp < HW) ? xb[(k0+kk)*HW + gp] : 0.f;
        }
        __syncthreads();
#pragma unroll 4
        for (int kk = 0; kk < 32; kk++){
            float4 wf = *(const float4*)&s_w[kk*260 + n0];
            u64 w0 = dup2(wf.x), w1d = dup2(wf.y), w2d = dup2(wf.z), w3d = dup2(wf.w);
            const u64* xp = (const u64*)(s_x + kk*64) + pg*8;
            u64 xv[8];
#pragma unroll
            for (int p = 0; p < 8; p++) xv[p] = xp[p];
#pragma unroll
            for (int p = 0; p < 8; p++){
                fma2(acc[0][p], xv[p], w0);
                fma2(acc[1][p], xv[p], w1d);
                fma2(acc[2][p], xv[p], w2d);
                fma2(acc[3][p], xv[p], w3d);
            }
        }
    }

    u64 psum[8];
#pragma unroll
    for (int p = 0; p < 8; p++) psum[p] = 0ull;
#pragma unroll
    for (int i = 0; i < 4; i++){
        float sc = g_scale_1[n0+i], bi = g_bias_1[n0+i], wv = w2[n0+i];
#pragma unroll
        for (int p = 0; p < 8; p++){
            float2 f = unpk(acc[i][p]);
            f.x = fmaxf(fmaf(sc, f.x, bi), 0.f) * wv;
            f.y = fmaxf(fmaf(sc, f.y, bi), 0.f) * wv;
            psum[p] = add2(psum[p], pack2(f.x, f.y));
        }
    }
    int lane = tid & 31, wrp = tid >> 5;
#pragma unroll
    for (int p = 0; p < 8; p++){
        u64 v = psum[p];
        v = add2(v, __shfl_xor_sync(0xffffffffu, v, 16));
        v = add2(v, __shfl_xor_sync(0xffffffffu, v, 8));
        v = add2(v, __shfl_xor_sync(0xffffffffu, v, 4));
        v = add2(v, __shfl_xor_sync(0xffffffffu, v, 2));
        v = add2(v, __shfl_xor_sync(0xffffffffu, v, 1));
        psum[p] = v;
    }
    if (lane == 0){
#pragma unroll
        for (int p = 0; p < 8; p++){
            float2 f = unpk(psum[p]);
            s_red[wrp][2*p] = f.x;
            s_red[wrp][2*p+1] = f.y;
        }
    }
    __syncthreads();
    if (tid < 64){
        int pg2 = tid >> 4, j = tid & 15;
        float v = s_red[2*pg2][j] + s_red[2*pg2+1][j];
        int gp = p0 + pg2*16 + j;
        if (gp < HW)
            out[(size_t)b*HW + gp] = 1.f / (1.f + expf(-(v + b2[0])));
    }
}

// ---------------- launch ----------------
extern "C" void kernel_launch(void* const* d_in, const int* in_sizes, int n_in,
                              void* d_out, int out_size){
    const float* large  = (const float*)d_in[0];
    const float* medium = (const float*)d_in[1];
    const float* small  = (const float*)d_in[2];
    const float* search = (const float*)d_in[3];
    const float* wt  = (const float*)d_in[4];
    const float* bt  = (const float*)d_in[5];
    const float* gt  = (const float*)d_in[6];
    const float* bet = (const float*)d_in[7];
    const float* mt  = (const float*)d_in[8];
    const float* vt  = (const float*)d_in[9];
    const float* ws  = (const float*)d_in[10];
    const float* bs  = (const float*)d_in[11];
    const float* gs  = (const float*)d_in[12];
    const float* bes = (const float*)d_in[13];
    const float* ms  = (const float*)d_in[14];
    const float* vs  = (const float*)d_in[15];
    const float* w1  = (const float*)d_in[16];
    const float* b1  = (const float*)d_in[17];
    const float* g1  = (const float*)d_in[18];
    const float* be1 = (const float*)d_in[19];
    const float* m1  = (const float*)d_in[20];
    const float* v1  = (const float*)d_in[21];
    const float* w2  = (const float*)d_in[22];
    const float* b2  = (const float*)d_in[23];
    float* out = (float*)d_out;

    float *lf, *mf, *sf, *lc, *mc, *sc;
    cudaGetSymbolAddress((void**)&lf, g_lf);
    cudaGetSymbolAddress((void**)&mf, g_mf);
    cudaGetSymbolAddress((void**)&sf, g_sf);
    cudaGetSymbolAddress((void**)&lc, g_lc);
    cudaGetSymbolAddress((void**)&mc, g_mc);
    cudaGetSymbolAddress((void**)&sc, g_sc);

    static cudaStream_t st1 = 0, st2 = 0;
    static cudaEvent_t evRoot = 0, evT = 0, evFork = 0, ev1 = 0, ev2 = 0;
    if (!st1){
        cudaStreamCreateWithFlags(&st1, cudaStreamNonBlocking);
        cudaStreamCreateWithFlags(&st2, cudaStreamNonBlocking);
        cudaEventCreateWithFlags(&evRoot, cudaEventDisableTiming);
        cudaEventCreateWithFlags(&evT, cudaEventDisableTiming);
        cudaEventCreateWithFlags(&evFork, cudaEventDisableTiming);
        cudaEventCreateWithFlags(&ev1, cudaEventDisableTiming);
        cudaEventCreateWithFlags(&ev2, cudaEventDisableTiming);
        cudaFuncSetAttribute(conv_search_mma,
                             cudaFuncAttributeMaxDynamicSharedMemorySize, CSM_BYTES);
    }

    prep_kernel<<<1, 256>>>(bt, gt, bet, mt, vt, bs, gs, bes, ms, vs, b1, g1, be1, m1, v1);

    // fork: tmpl_all runs on st1 concurrently with wt_trans + conv on stream 0
    cudaEventRecord(evRoot, 0);
    cudaStreamWaitEvent(st1, evRoot, 0);
    tmpl_all<<<dim3(64, 4), 512, 0, st1>>>(large, medium, small, wt, lf, mf, sf);
    cudaEventRecord(evT, st1);

    wt_trans<<<(9*C*C + 255)/256, 256>>>(ws);
    conv_search_mma<<<dim3(64, 7, 4), 256, CSM_BYTES>>>(search);
    cudaStreamWaitEvent(0, evT, 0);

    // fork three independent corr->head chains
    cudaEventRecord(evFork, 0);
    cudaStreamWaitEvent(st1, evFork, 0);
    cudaStreamWaitEvent(st2, evFork, 0);

    corr_v2<7, 2, 27><<<dim3(64, 32), 256>>>(lf, lc);
    head_kernel<<<dim3(12, 64), 256>>>(lc, 729, w1, w2, b2, out);

    corr_v2<5, 0, 25><<<dim3(64, 32), 256, 0, st1>>>(mf, mc);
    head_kernel<<<dim3(10, 64), 256, 0, st1>>>(mc, 625, w1, w2, b2, out + 64*729);
    cudaEventRecord(ev1, st1);

    corr_v2<3, 0, 27><<<dim3(64, 32), 256, 0, st2>>>(sf, sc);
    head_kernel<<<dim3(12, 64), 256, 0, st2>>>(sc, 729, w1, w2, b2, out + 64*729 + 64*625);
    cudaEventRecord(ev2, st2);

    cudaStreamWaitEvent(0, ev1, 0);
    cudaStreamWaitEvent(0, ev2, 0);
}

// round 14
// speedup vs baseline: 1.2122x; 1.1339x over previous
#include <cuda_runtime.h>
#include <cuda_fp16.h>
#include <math.h>

#define B 64
#define C 256

typedef unsigned long long u64;
typedef unsigned int u32;

// ---------------- f32x2 packed-math helpers ----------------
__device__ __forceinline__ u64 pack2(float lo, float hi){
    u64 r; asm("mov.b64 %0, {%1, %2};" : "=l"(r) : "f"(lo), "f"(hi)); return r;
}
__device__ __forceinline__ u64 dup2(float v){
    u64 r; asm("mov.b64 %0, {%1, %1};" : "=l"(r) : "f"(v)); return r;
}
__device__ __forceinline__ void fma2(u64 &d, u64 a, u64 b){
    asm("fma.rn.f32x2 %0, %1, %2, %0;" : "+l"(d) : "l"(a), "l"(b));
}
__device__ __forceinline__ u64 add2(u64 a, u64 b){
    u64 d; asm("add.rn.f32x2 %0, %1, %2;" : "=l"(d) : "l"(a), "l"(b)); return d;
}
__device__ __forceinline__ float2 unpk(u64 v){
    float2 f; asm("mov.b64 {%0, %1}, %2;" : "=f"(f.x), "=f"(f.y) : "l"(v)); return f;
}
__device__ __forceinline__ u32 h2pack(__half a, __half b){
    return ((u32)__half_as_ushort(b) << 16) | (u32)__half_as_ushort(a);
}
__device__ __forceinline__ u32 smem_u32(const void* p){
    u32 a; asm("{ .reg .u64 t; cvta.to.shared.u64 t, %1; cvt.u32.u64 %0, t; }" : "=r"(a) : "l"(p));
    return a;
}

// ---------------- scratch ----------------
__device__ float g_lf[B*C*7*7];
__device__ float g_mf[B*C*5*5];
__device__ float g_sf[B*C*3*3];
__device__ float g_s [B*C*29*29];
__device__ float g_lc[B*C*27*27];
__device__ float g_mc[B*C*25*25];
__device__ float g_sc[B*C*27*27];
__device__ __align__(16) __half g_wth[9*C*C];  // weights x1024, fp16 hi, [khw][oc][ic]
__device__ __align__(16) __half g_wtl[9*C*C];  // weights x1024, fp16 lo
__device__ float g_scale_t[C], g_bias_t[C];
__device__ float g_scale_s[C], g_bias_s[C];
__device__ float g_scale_1[C], g_bias_1[C];

// ---------------- BN folding ----------------
__global__ void prep_kernel(const float* bt,const float* gt,const float* bet,const float* mt,const float* vt,
                            const float* bs,const float* gs,const float* bes,const float* ms,const float* vs,
                            const float* b1,const float* g1,const float* be1,const float* m1,const float* v1){
    int c = threadIdx.x;
    { float inv = gt[c]*rsqrtf(vt[c]+1e-5f); g_scale_t[c]=inv; g_bias_t[c]=bt[c]*inv + bet[c] - mt[c]*inv; }
    { float inv = gs[c]*rsqrtf(vs[c]+1e-5f); g_scale_s[c]=inv; g_bias_s[c]=bs[c]*inv + bes[c] - ms[c]*inv; }
    { float inv = g1[c]*rsqrtf(v1[c]+1e-5f); g_scale_1[c]=inv; g_bias_1[c]=b1[c]*inv + be1[c] - m1[c]*inv; }
}

// ---------------- weight transpose + fp16 hi/lo split (x1024) ----------------
__global__ void wt_trans(const float* __restrict__ w){
    int idx = blockIdx.x * 256 + threadIdx.x;
    if (idx < 9*C*C){
        int khw = idx % 9;
        int rest = idx / 9;          // oc*256 + ic
        int ic = rest & 255;
        int oc = rest >> 8;
        float v = w[idx] * 1024.0f;
        __half h = __float2half_rn(v);
        size_t o = ((size_t)khw*C + oc)*C + ic;
        g_wth[o] = h;
        g_wtl[o] = __float2half_rn(v - __half2float(h));
    }
}

// ---------------- merged template conv 3x3 + BN + ReLU, f32x2 ----------------
template<int W, int NP>
__device__ __forceinline__ void row3(const float* ip, const u64* wdA, const u64* wdB,
                                     u64* aA, u64* aB){
#pragma unroll
    for (int kh = 0; kh < 3; kh++){
        float rv[2*NP+2];
#pragma unroll
        for (int j = 0; j < 2*NP+2; j++) rv[j] = ip[kh*W + j];
        u64 pe[NP+1], po[NP];
#pragma unroll
        for (int p = 0; p <= NP; p++) pe[p] = pack2(rv[2*p], rv[2*p+1]);
#pragma unroll
        for (int p = 0; p < NP; p++) po[p] = pack2(rv[2*p+1], rv[2*p+2]);
#pragma unroll
        for (int p = 0; p < NP; p++){
            fma2(aA[p], pe[p],   wdA[kh*3+0]);
            fma2(aA[p], po[p],   wdA[kh*3+1]);
            fma2(aA[p], pe[p+1], wdA[kh*3+2]);
            fma2(aB[p], pe[p],   wdB[kh*3+0]);
            fma2(aB[p], po[p],   wdB[kh*3+1]);
            fma2(aB[p], pe[p+1], wdB[kh*3+2]);
        }
    }
}

template<int OH, int NP>
__device__ __forceinline__ void tmpl_store(float* out, int b, int oc0, int row,
                                           const u64* aA, const u64* aB){
    float scA = g_scale_t[oc0],   biA = g_bias_t[oc0];
    float scB = g_scale_t[oc0+1], biB = g_bias_t[oc0+1];
    float* pA = out + (((size_t)b*C + oc0  )*OH + row)*OH;
    float* pB = out + (((size_t)b*C + oc0+1)*OH + row)*OH;
#pragma unroll
    for (int p = 0; p < NP; p++){
        float2 fa = unpk(aA[p]), fb = unpk(aB[p]);
        int col = 2*p;
        if (col < OH){
            float va = fmaf(scA, fa.x, biA); pA[col] = va > 0.f ? va : 0.f;
            float vb = fmaf(scB, fb.x, biB); pB[col] = vb > 0.f ? vb : 0.f;
        }
        if (col+1 < OH){
            float va = fmaf(scA, fa.y, biA); pA[col+1] = va > 0.f ? va : 0.f;
            float vb = fmaf(scB, fb.y, biB); pB[col+1] = vb > 0.f ? vb : 0.f;
        }
    }
}

__global__ void __launch_bounds__(512) tmpl_all(const float* __restrict__ lin,
                                                const float* __restrict__ min_,
                                                const float* __restrict__ sin_,
                                                const float* __restrict__ w,
                                                float* lo, float* mo, float* so){
    __shared__ __align__(16) float s_in[16*155 + 4];
    __shared__ __align__(16) float s_w[144*66];
    int tid = threadIdx.x;
    int ocp = tid & 31, slot = tid >> 5;
    int b = blockIdx.x, ocbase = blockIdx.y * 64;
    int oc0 = ocbase + ocp*2;

    u64 aA[4] = {0,0,0,0}, aB[4] = {0,0,0,0};

    for (int ic0 = 0; ic0 < C; ic0 += 16){
        __syncthreads();
#pragma unroll 1
        for (int idx = tid; idx < 16*155; idx += 512){
            int ic = idx / 155, r = idx % 155;
            size_t cb = (size_t)b*C + ic0 + ic;
            float v;
            if (r < 81)       v = lin [cb*81 + r];
            else if (r < 130) v = min_[cb*49 + (r-81)];
            else              v = sin_[cb*25 + (r-130)];
            s_in[ic*155 + r] = v;
        }
#pragma unroll 1
        for (int idx = tid; idx < 64*144; idx += 512){
            int oc = idx / 144, r = idx % 144;
            s_w[r*66 + oc] = w[(size_t)(ocbase+oc)*2304 + (size_t)ic0*9 + r];
        }
        __syncthreads();

        if (slot < 7){
            int row = slot;
#pragma unroll 1
            for (int ic = 0; ic < 16; ic++){
                u64 wdA[9], wdB[9];
#pragma unroll
                for (int k = 0; k < 9; k++){
                    u64 pr = *(const u64*)&s_w[(ic*9+k)*66 + ocp*2];
                    float2 f = unpk(pr);
                    wdA[k] = dup2(f.x); wdB[k] = dup2(f.y);
                }
                row3<9,4>(s_in + ic*155 + row*9, wdA, wdB, aA, aB);
            }
        } else if (slot < 12){
            int row = slot - 7;
#pragma unroll 1
            for (int ic = 0; ic < 16; ic++){
                u64 wdA[9], wdB[9];
#pragma unroll
                for (int k = 0; k < 9; k++){
                    u64 pr = *(const u64*)&s_w[(ic*9+k)*66 + ocp*2];
                    float2 f = unpk(pr);
                    wdA[k] = dup2(f.x); wdB[k] = dup2(f.y);
                }
                row3<7,3>(s_in + ic*155 + 81 + row*7, wdA, wdB, aA, aB);
            }
        } else if (slot < 15){
            int row = slot - 12;
#pragma unroll 1
            for (int ic = 0; ic < 16; ic++){
                u64 wdA[9], wdB[9];
#pragma unroll
                for (int k = 0; k < 9; k++){
                    u64 pr = *(const u64*)&s_w[(ic*9+k)*66 + ocp*2];
                    float2 f = unpk(pr);
                    wdA[k] = dup2(f.x); wdB[k] = dup2(f.y);
                }
                row3<5,2>(s_in + ic*155 + 130 + row*5, wdA, wdB, aA, aB);
            }
        }
    }

    if (slot < 7)       tmpl_store<7,4>(lo, b, oc0, slot,      aA, aB);
    else if (slot < 12) tmpl_store<5,3>(mo, b, oc0, slot - 7,  aA, aB);
    else if (slot < 15) tmpl_store<3,2>(so, b, oc0, slot - 12, aA, aB);
}

// ---------------- search conv: fp16-split mma.m16n8k16 + ldmatrix ----------------
#define SA_ROWS 248
#define SA_STRIDE 20
#define SA_N (SA_ROWS*SA_STRIDE)
#define SB_STRIDE 20
#define SB_N (64*SB_STRIDE)
#define CSM_BYTES ((2*SA_N + 2*SB_N) * 4)

#define MMA16(acc, a0,a1,a2,a3, b0,b1) \
    asm volatile( \
        "mma.sync.aligned.m16n8k16.row.col.f32.f16.f16.f32 " \
        "{%0,%1,%2,%3}, {%4,%5,%6,%7}, {%8,%9}, {%0,%1,%2,%3};" \
        : "+f"((acc)[0]), "+f"((acc)[1]), "+f"((acc)[2]), "+f"((acc)[3]) \
        : "r"(a0), "r"(a1), "r"(a2), "r"(a3), "r"(b0), "r"(b1))

#define LDSM4(r0,r1,r2,r3, addr) \
    asm volatile("ldmatrix.sync.aligned.m8n8.x4.shared.b16 {%0,%1,%2,%3}, [%4];" \
        : "=r"(r0), "=r"(r1), "=r"(r2), "=r"(r3) : "r"(addr))

__global__ void __launch_bounds__(256) conv_search_mma(const float* __restrict__ in){
    extern __shared__ __align__(16) u32 smem_dyn[];
    u32* sa_h = smem_dyn;
    u32* sa_l = sa_h + SA_N;
    u32* sb_h = sa_l + SA_N;
    u32* sb_l = sb_h + SB_N;

    int tid = threadIdx.x;
    int lane = tid & 31, wid = tid >> 5;
    int g = lane >> 2, t = lane & 3;
    int wm = wid & 3, wn = wid >> 2;
    int b = blockIdx.x;
    int pstart = blockIdx.y * 128;
    int ocb0 = blockIdx.z * 64;
    int r_first = pstart / 29;

    // epilogue pixel mapping (accumulator layout: rows g, g+8; cols 2t, 2t+1)
    int pxv[2][2];
    bool pvalid[2][2];
#pragma unroll
    for (int mf = 0; mf < 2; mf++)
#pragma unroll
        for (int h = 0; h < 2; h++){
            int px = pstart + wm*32 + mf*16 + g + h*8;
            pvalid[mf][h] = (px < 841);
            pxv[mf][h] = px < 841 ? px : 840;
        }

    // ldmatrix A addressing: lane -> row ((lane>>3)&1)*8 + (lane&7), k half by lane>=16
    int rrow = ((lane >> 3) & 1) * 8 + (lane & 7);
    int kwA = (lane & 16) ? 4 : 0;
    u32 aoff[2];
#pragma unroll
    for (int mf = 0; mf < 2; mf++){
        int pA = pstart + wm*32 + mf*16 + rrow;
        int pAc = pA < 841 ? pA : 840;
        int rA = pAc / 29, cA = pAc - rA*29;
        int rcA = (rA - r_first)*31 + cA;
        aoff[mf] = (u32)((rcA*SA_STRIDE + kwA) * 4);
    }
    // ldmatrix B addressing: matrices [q-oc0-7 k-lo, q-oc0-7 k-hi, q-oc8-15 k-lo, q-oc8-15 k-hi]
    int ocq = ((lane >> 4) & 1) * 8 + (lane & 7);
    int kwB = (lane & 8) ? 4 : 0;
    u32 boff[2];
#pragma unroll
    for (int q = 0; q < 2; q++)
        boff[q] = (u32)(((wn*32 + q*16 + ocq)*SB_STRIDE + kwB) * 4);

    u32 sah_b = smem_u32(sa_h), sal_b = smem_u32(sa_l);
    u32 sbh_b = smem_u32(sb_h), sbl_b = smem_u32(sb_l);

    float acc[2][4][4];
#pragma unroll
    for (int mf = 0; mf < 2; mf++)
#pragma unroll
        for (int nf = 0; nf < 4; nf++)
#pragma unroll
            for (int i = 0; i < 4; i++) acc[mf][nf][i] = 0.f;

    const float* inb = in + (size_t)b * C * 961;

    for (int ic0 = 0; ic0 < C; ic0 += 32){
        __syncthreads();
        // stage A (hi/lo fp16x2, 16 u32 per row = 32 ic)
#pragma unroll 1
        for (int icp = 0; icp < 16; icp++){
            int rc = tid;
            if (rc < SA_ROWS){
                int gidx = r_first*31 + rc;
                int ic = ic0 + icp*2;
                float v0 = 0.f, v1 = 0.f;
                if (gidx < 961){
                    v0 = inb[ic*961 + gidx];
                    v1 = inb[(ic+1)*961 + gidx];
                }
                __half h0 = __float2half_rn(v0), h1 = __float2half_rn(v1);
                float r0 = v0 - __half2float(h0), r1 = v1 - __half2float(h1);
                sa_h[rc*SA_STRIDE + icp] = h2pack(h0, h1);
                sa_l[rc*SA_STRIDE + icp] = h2pack(__float2half_rn(r0), __float2half_rn(r1));
            }
        }
#pragma unroll 1
        for (int khw = 0; khw < 9; khw++){
            __syncthreads();
            // stage B from pre-split fp16 planes: 64 oc x 4 q4 = 256 items, 1 per thread
            {
                const __half* wh = g_wth + ((size_t)khw*C + ocb0)*C + ic0;
                const __half* wl = g_wtl + ((size_t)khw*C + ocb0)*C + ic0;
                int oc = tid >> 2, q4 = tid & 3;
                uint4 vh = *(const uint4*)(wh + (size_t)oc*C + q4*8);
                uint4 vl = *(const uint4*)(wl + (size_t)oc*C + q4*8);
                *(uint4*)(sb_h + oc*SB_STRIDE + q4*4) = vh;
                *(uint4*)(sb_l + oc*SB_STRIDE + q4*4) = vl;
            }
            __syncthreads();
            int kh = khw / 3, kw = khw - kh*3;
            u32 shb = (u32)((kh*31 + kw) * SA_STRIDE * 4);
#pragma unroll
            for (int ks = 0; ks < 2; ks++){
                u32 ksb = ks * 32;
                u32 bh[8], bl[8];
                LDSM4(bh[0], bh[1], bh[2], bh[3], sbh_b + boff[0] + ksb);
                LDSM4(bh[4], bh[5], bh[6], bh[7], sbh_b + boff[1] + ksb);
                LDSM4(bl[0], bl[1], bl[2], bl[3], sbl_b + boff[0] + ksb);
                LDSM4(bl[4], bl[5], bl[6], bl[7], sbl_b + boff[1] + ksb);
#pragma unroll
                for (int mf = 0; mf < 2; mf++){
                    u32 ah[4], al[4];
                    LDSM4(ah[0], ah[1], ah[2], ah[3], sah_b + aoff[mf] + shb + ksb);
                    LDSM4(al[0], al[1], al[2], al[3], sal_b + aoff[mf] + shb + ksb);
#pragma unroll
                    for (int nf = 0; nf < 4; nf++){
                        MMA16(acc[mf][nf], ah[0], ah[1], ah[2], ah[3], bh[nf*2], bh[nf*2+1]);
                        MMA16(acc[mf][nf], ah[0], ah[1], ah[2], ah[3], bl[nf*2], bl[nf*2+1]);
                        MMA16(acc[mf][nf], al[0], al[1], al[2], al[3], bh[nf*2], bh[nf*2+1]);
                    }
                }
            }
        }
    }

    const float inv1024 = 0.0009765625f;
#pragma unroll
    for (int nf = 0; nf < 4; nf++){
        int oc0 = ocb0 + wn*32 + nf*8 + 2*t;
        int oc1 = oc0 + 1;
        float sc0 = g_scale_s[oc0] * inv1024, bi0 = g_bias_s[oc0];
        float sc1 = g_scale_s[oc1] * inv1024, bi1 = g_bias_s[oc1];
#pragma unroll
        for (int mf = 0; mf < 2; mf++){
            if (pvalid[mf][0]){
                float v0 = fmaf(sc0, acc[mf][nf][0], bi0);
                float v1 = fmaf(sc1, acc[mf][nf][1], bi1);
                g_s[((size_t)b*C + oc0)*841 + pxv[mf][0]] = v0 > 0.f ? v0 : 0.f;
                g_s[((size_t)b*C + oc1)*841 + pxv[mf][0]] = v1 > 0.f ? v1 : 0.f;
            }
            if (pvalid[mf][1]){
                float v2 = fmaf(sc0, acc[mf][nf][2], bi0);
                float v3 = fmaf(sc1, acc[mf][nf][3], bi1);
                g_s[((size_t)b*C + oc0)*841 + pxv[mf][1]] = v2 > 0.f ? v2 : 0.f;
                g_s[((size_t)b*C + oc1)*841 + pxv[mf][1]] = v3 > 0.f ? v3 : 0.f;
            }
        }
    }
}

// ---------------- corr v2: warp = channel, lane = output row, f32x2 --------------
template<int TS, int PAD, int OS>
__global__ void __launch_bounds__(256) corr_v2(const float* __restrict__ t,
                                               float* __restrict__ out){
    constexpr int R = OS + TS - 1;
    constexpr int STRIDE = 35;
    constexpr int NPAIR = (OS + 1) / 2;
    constexpr int VW = 2*NPAIR + TS - 1;
    constexpr int NPE = VW / 2;
    __shared__ float s_pad[8 * R * STRIDE];
    __shared__ float s_t[8 * TS * TS];
    int tid = threadIdx.x;
    int wrp = tid >> 5, lane = tid & 31;
    int b = blockIdx.x;
    int c0 = blockIdx.y * 8;

#pragma unroll 1
    for (int idx = tid; idx < 8 * R * STRIDE; idx += 256) s_pad[idx] = 0.f;
    __syncthreads();
    const float* sb = g_s + ((size_t)b*C + c0) * 841;
#pragma unroll 1
    for (int idx = tid; idx < 8 * 841; idx += 256){
        int ch = idx / 841, rem = idx - ch*841;
        int row = rem / 29, col = rem - row*29;
        s_pad[ch*R*STRIDE + (row + PAD)*STRIDE + col + PAD] = sb[ch*841 + rem];
    }
    const float* tb = t + ((size_t)b*C + c0) * TS * TS;
#pragma unroll 1
    for (int idx = tid; idx < 8 * TS * TS; idx += 256) s_t[idx] = tb[idx];
    __syncthreads();

    if (lane < OS){
        const float* sp = s_pad + wrp*R*STRIDE + lane*STRIDE;
        const float* tp = s_t + wrp*TS*TS;
        u64 a[NPAIR];
#pragma unroll
        for (int p = 0; p < NPAIR; p++) a[p] = 0ull;
#pragma unroll
        for (int trow = 0; trow < TS; trow++){
            u64 wd[TS];
#pragma unroll
            for (int j = 0; j < TS; j++) wd[j] = dup2(tp[trow*TS + j]);
            float v[VW];
#pragma unroll
            for (int k = 0; k < VW; k++) v[k] = sp[trow*STRIDE + k];
            u64 pe[NPE], po[NPE-1];
#pragma unroll
            for (int k = 0; k < NPE; k++) pe[k] = pack2(v[2*k], v[2*k+1]);
#pragma unroll
            for (int k = 0; k < NPE-1; k++) po[k] = pack2(v[2*k+1], v[2*k+2]);
#pragma unroll
            for (int j = 0; j < TS; j++){
                if (j & 1){
#pragma unroll
                    for (int p = 0; p < NPAIR; p++) fma2(a[p], po[p + (j>>1)], wd[j]);
                } else {
#pragma unroll
                    for (int p = 0; p < NPAIR; p++) fma2(a[p], pe[p + (j>>1)], wd[j]);
                }
            }
        }
        float* op = out + (((size_t)b*C + c0 + wrp)*OS + lane)*OS;
#pragma unroll
        for (int p = 0; p < NPAIR; p++){
            float2 f = unpk(a[p]);
            op[2*p] = f.x;
            if (2*p + 1 < OS) op[2*p + 1] = f.y;
        }
    }
}

// ---------------- head v2: thread = 4 n x 16 px --------------------------------
__global__ void __launch_bounds__(256) head_kernel(const float* __restrict__ x, int HW,
                                                   const float* __restrict__ w1,
                                                   const float* __restrict__ w2,
                                                   const float* __restrict__ b2,
                                                   float* __restrict__ out){
    __shared__ __align__(16) float s_w[32 * 260];
    __shared__ __align__(16) float s_x[32 * 64];
    __shared__ float s_red[8][16];
    int tid = threadIdx.x;
    int nq = tid & 63;
    int pg = tid >> 6;
    int n0 = nq * 4;
    int b = blockIdx.y;
    int p0 = blockIdx.x * 64;
    const float* xb = x + (size_t)b * C * HW;

    u64 acc[4][8];
#pragma unroll
    for (int i = 0; i < 4; i++)
#pragma unroll
        for (int p = 0; p < 8; p++) acc[i][p] = 0ull;

    for (int k0 = 0; k0 < C; k0 += 32){
        __syncthreads();
#pragma unroll 1
        for (int idx = tid; idx < 8192; idx += 256){
            int kk = idx & 31, n = idx >> 5;
            s_w[kk*260 + n] = w1[n*C + k0 + kk];
        }
#pragma unroll 1
        for (int idx = tid; idx < 2048; idx += 256){
            int p = idx & 63, kk = idx >> 6;
            int gp = p0 + p;
            s_x[kk*64 + p] = (gp < HW) ? xb[(k0+kk)*HW + gp] : 0.f;
        }
        __syncthreads();
#pragma unroll 4
        for (int kk = 0; kk < 32; kk++){
            float4 wf = *(const float4*)&s_w[kk*260 + n0];
            u64 w0 = dup2(wf.x), w1d = dup2(wf.y), w2d = dup2(wf.z), w3d = dup2(wf.w);
            const u64* xp = (const u64*)(s_x + kk*64) + pg*8;
            u64 xv[8];
#pragma unroll
            for (int p = 0; p < 8; p++) xv[p] = xp[p];
#pragma unroll
            for (int p = 0; p < 8; p++){
                fma2(acc[0][p], xv[p], w0);
                fma2(acc[1][p], xv[p], w1d);
                fma2(acc[2][p], xv[p], w2d);
                fma2(acc[3][p], xv[p], w3d);
            }
        }
    }

    u64 psum[8];
#pragma unroll
    for (int p = 0; p < 8; p++) psum[p] = 0ull;
#pragma unroll
    for (int i = 0; i < 4; i++){
        float sc = g_scale_1[n0+i], bi = g_bias_1[n0+i], wv = w2[n0+i];
#pragma unroll
        for (int p = 0; p < 8; p++){
            float2 f = unpk(acc[i][p]);
            f.x = fmaxf(fmaf(sc, f.x, bi), 0.f) * wv;
            f.y = fmaxf(fmaf(sc, f.y, bi), 0.f) * wv;
            psum[p] = add2(psum[p], pack2(f.x, f.y));
        }
    }
    int lane = tid & 31, wrp = tid >> 5;
#pragma unroll
    for (int p = 0; p < 8; p++){
        u64 v = psum[p];
        v = add2(v, __shfl_xor_sync(0xffffffffu, v, 16));
        v = add2(v, __shfl_xor_sync(0xffffffffu, v, 8));
        v = add2(v, __shfl_xor_sync(0xffffffffu, v, 4));
        v = add2(v, __shfl_xor_sync(0xffffffffu, v, 2));
        v = add2(v, __shfl_xor_sync(0xffffffffu, v, 1));
        psum[p] = v;
    }
    if (lane == 0){
#pragma unroll
        for (int p = 0; p < 8; p++){
            float2 f = unpk(psum[p]);
            s_red[wrp][2*p] = f.x;
            s_red[wrp][2*p+1] = f.y;
        }
    }
    __syncthreads();
    if (tid < 64){
        int pg2 = tid >> 4, j = tid & 15;
        float v = s_red[2*pg2][j] + s_red[2*pg2+1][j];
        int gp = p0 + pg2*16 + j;
        if (gp < HW)
            out[(size_t)b*HW + gp] = 1.f / (1.f + expf(-(v + b2[0])));
    }
}

// ---------------- launch ----------------
extern "C" void kernel_launch(void* const* d_in, const int* in_sizes, int n_in,
                              void* d_out, int out_size){
    const float* large  = (const float*)d_in[0];
    const float* medium = (const float*)d_in[1];
    const float* small  = (const float*)d_in[2];
    const float* search = (const float*)d_in[3];
    const float* wt  = (const float*)d_in[4];
    const float* bt  = (const float*)d_in[5];
    const float* gt  = (const float*)d_in[6];
    const float* bet = (const float*)d_in[7];
    const float* mt  = (const float*)d_in[8];
    const float* vt  = (const float*)d_in[9];
    const float* ws  = (const float*)d_in[10];
    const float* bs  = (const float*)d_in[11];
    const float* gs  = (const float*)d_in[12];
    const float* bes = (const float*)d_in[13];
    const float* ms  = (const float*)d_in[14];
    const float* vs  = (const float*)d_in[15];
    const float* w1  = (const float*)d_in[16];
    const float* b1  = (const float*)d_in[17];
    const float* g1  = (const float*)d_in[18];
    const float* be1 = (const float*)d_in[19];
    const float* m1  = (const float*)d_in[20];
    const float* v1  = (const float*)d_in[21];
    const float* w2  = (const float*)d_in[22];
    const float* b2  = (const float*)d_in[23];
    float* out = (float*)d_out;

    float *lf, *mf, *sf, *lc, *mc, *sc;
    cudaGetSymbolAddress((void**)&lf, g_lf);
    cudaGetSymbolAddress((void**)&mf, g_mf);
    cudaGetSymbolAddress((void**)&sf, g_sf);
    cudaGetSymbolAddress((void**)&lc, g_lc);
    cudaGetSymbolAddress((void**)&mc, g_mc);
    cudaGetSymbolAddress((void**)&sc, g_sc);

    static cudaStream_t st1 = 0, st2 = 0;
    static cudaEvent_t evRoot = 0, evT = 0, evFork = 0, ev1 = 0, ev2 = 0;
    if (!st1){
        cudaStreamCreateWithFlags(&st1, cudaStreamNonBlocking);
        cudaStreamCreateWithFlags(&st2, cudaStreamNonBlocking);
        cudaEventCreateWithFlags(&evRoot, cudaEventDisableTiming);
        cudaEventCreateWithFlags(&evT, cudaEventDisableTiming);
        cudaEventCreateWithFlags(&evFork, cudaEventDisableTiming);
        cudaEventCreateWithFlags(&ev1, cudaEventDisableTiming);
        cudaEventCreateWithFlags(&ev2, cudaEventDisableTiming);
        cudaFuncSetAttribute(conv_search_mma,
                             cudaFuncAttributeMaxDynamicSharedMemorySize, CSM_BYTES);
    }

    prep_kernel<<<1, 256>>>(bt, gt, bet, mt, vt, bs, gs, bes, ms, vs, b1, g1, be1, m1, v1);

    // fork: tmpl_all runs on st1 concurrently with wt_trans + conv on stream 0
    cudaEventRecord(evRoot, 0);
    cudaStreamWaitEvent(st1, evRoot, 0);
    tmpl_all<<<dim3(64, 4), 512, 0, st1>>>(large, medium, small, wt, lf, mf, sf);
    cudaEventRecord(evT, st1);

    wt_trans<<<(9*C*C + 255)/256, 256>>>(ws);
    conv_search_mma<<<dim3(64, 7, 4), 256, CSM_BYTES>>>(search);
    cudaStreamWaitEvent(0, evT, 0);

    // fork three independent corr->head chains
    cudaEventRecord(evFork, 0);
    cudaStreamWaitEvent(st1, evFork, 0);
    cudaStreamWaitEvent(st2, evFork, 0);

    corr_v2<7, 2, 27><<<dim3(64, 32), 256>>>(lf, lc);
    head_kernel<<<dim3(12, 64), 256>>>(lc, 729, w1, w2, b2, out);

    corr_v2<5, 0, 25><<<dim3(64, 32), 256, 0, st1>>>(mf, mc);
    head_kernel<<<dim3(10, 64), 256, 0, st1>>>(mc, 625, w1, w2, b2, out + 64*729);
    cudaEventRecord(ev1, st1);

    corr_v2<3, 0, 27><<<dim3(64, 32), 256, 0, st2>>>(sf, sc);
    head_kernel<<<dim3(12, 64), 256, 0, st2>>>(sc, 729, w1, w2, b2, out + 64*729 + 64*625);
    cudaEventRecord(ev2, st2);

    cudaStreamWaitEvent(0, ev1, 0);
    cudaStreamWaitEvent(0, ev2, 0);
}

// round 15
// speedup vs baseline: 1.6851x; 1.3901x over previous
#include <cuda_runtime.h>
#include <cuda_fp16.h>
#include <math.h>

#define B 64
#define C 256
#define HP_TOTAL (64*(729+625+729))

typedef unsigned long long u64;
typedef unsigned int u32;

// ---------------- f32x2 packed-math helpers ----------------
__device__ __forceinline__ u64 pack2(float lo, float hi){
    u64 r; asm("mov.b64 %0, {%1, %2};" : "=l"(r) : "f"(lo), "f"(hi)); return r;
}
__device__ __forceinline__ u64 dup2(float v){
    u64 r; asm("mov.b64 %0, {%1, %1};" : "=l"(r) : "f"(v)); return r;
}
__device__ __forceinline__ void fma2(u64 &d, u64 a, u64 b){
    asm("fma.rn.f32x2 %0, %1, %2, %0;" : "+l"(d) : "l"(a), "l"(b));
}
__device__ __forceinline__ u64 add2(u64 a, u64 b){
    u64 d; asm("add.rn.f32x2 %0, %1, %2;" : "=l"(d) : "l"(a), "l"(b)); return d;
}
__device__ __forceinline__ float2 unpk(u64 v){
    float2 f; asm("mov.b64 {%0, %1}, %2;" : "=f"(f.x), "=f"(f.y) : "l"(v)); return f;
}
__device__ __forceinline__ u32 h2pack(__half a, __half b){
    return ((u32)__half_as_ushort(b) << 16) | (u32)__half_as_ushort(a);
}
__device__ __forceinline__ u32 smem_u32(const void* p){
    u32 a; asm("{ .reg .u64 t; cvta.to.shared.u64 t, %1; cvt.u32.u64 %0, t; }" : "=r"(a) : "l"(p));
    return a;
}

// ---------------- scratch ----------------
__device__ float g_lf[B*C*7*7];
__device__ float g_mf[B*C*5*5];
__device__ float g_sf[B*C*3*3];
__device__ float g_s [B*C*29*29];
__device__ float g_lc[B*C*27*27];
__device__ float g_mc[B*C*25*25];
__device__ float g_sc[B*C*27*27];
__device__ float g_hp[HP_TOTAL];               // head partial sums
__device__ __align__(16) __half g_wth[9*C*C];  // conv weights x1024, fp16 hi
__device__ __align__(16) __half g_wtl[9*C*C];  // conv weights x1024, fp16 lo
__device__ __align__(16) __half g_w1h[C*C];    // head w1 x1024, fp16 hi [n][k]
__device__ __align__(16) __half g_w1l[C*C];    // head w1 x1024, fp16 lo
__device__ float g_scale_t[C], g_bias_t[C];
__device__ float g_scale_s[C], g_bias_s[C];
__device__ float g_scale_1[C], g_bias_1[C];

// ---------------- BN folding ----------------
__global__ void prep_kernel(const float* bt,const float* gt,const float* bet,const float* mt,const float* vt,
                            const float* bs,const float* gs,const float* bes,const float* ms,const float* vs,
                            const float* b1,const float* g1,const float* be1,const float* m1,const float* v1){
    int c = threadIdx.x;
    { float inv = gt[c]*rsqrtf(vt[c]+1e-5f); g_scale_t[c]=inv; g_bias_t[c]=bt[c]*inv + bet[c] - mt[c]*inv; }
    { float inv = gs[c]*rsqrtf(vs[c]+1e-5f); g_scale_s[c]=inv; g_bias_s[c]=bs[c]*inv + bes[c] - ms[c]*inv; }
    { float inv = g1[c]*rsqrtf(v1[c]+1e-5f); g_scale_1[c]=inv; g_bias_1[c]=b1[c]*inv + be1[c] - m1[c]*inv; }
}

// ---------------- conv weight transpose + fp16 hi/lo split (x1024) ----------------
__global__ void wt_trans(const float* __restrict__ w){
    int idx = blockIdx.x * 256 + threadIdx.x;
    if (idx < 9*C*C){
        int khw = idx % 9;
        int rest = idx / 9;
        int ic = rest & 255;
        int oc = rest >> 8;
        float v = w[idx] * 1024.0f;
        __half h = __float2half_rn(v);
        size_t o = ((size_t)khw*C + oc)*C + ic;
        g_wth[o] = h;
        g_wtl[o] = __float2half_rn(v - __half2float(h));
    }
}

// ---------------- head w1 fp16 hi/lo split (x1024), layout already [n][k] ------
__global__ void w1_split(const float* __restrict__ w1){
    int idx = blockIdx.x * 256 + threadIdx.x;
    if (idx < C*C){
        float v = w1[idx] * 1024.0f;
        __half h = __float2half_rn(v);
        g_w1h[idx] = h;
        g_w1l[idx] = __float2half_rn(v - __half2float(h));
    }
}

__global__ void zero_hp(){
    int i = blockIdx.x * 256 + threadIdx.x;
    if (i < HP_TOTAL) g_hp[i] = 0.f;
}

__global__ void final_sig(const float* __restrict__ b2, float* __restrict__ out){
    int i = blockIdx.x * 256 + threadIdx.x;
    if (i < HP_TOTAL) out[i] = 1.f / (1.f + expf(-(g_hp[i] + b2[0])));
}

// ---------------- merged template conv 3x3 + BN + ReLU, f32x2 ----------------
template<int W, int NP>
__device__ __forceinline__ void row3(const float* ip, const u64* wdA, const u64* wdB,
                                     u64* aA, u64* aB){
#pragma unroll
    for (int kh = 0; kh < 3; kh++){
        float rv[2*NP+2];
#pragma unroll
        for (int j = 0; j < 2*NP+2; j++) rv[j] = ip[kh*W + j];
        u64 pe[NP+1], po[NP];
#pragma unroll
        for (int p = 0; p <= NP; p++) pe[p] = pack2(rv[2*p], rv[2*p+1]);
#pragma unroll
        for (int p = 0; p < NP; p++) po[p] = pack2(rv[2*p+1], rv[2*p+2]);
#pragma unroll
        for (int p = 0; p < NP; p++){
            fma2(aA[p], pe[p],   wdA[kh*3+0]);
            fma2(aA[p], po[p],   wdA[kh*3+1]);
            fma2(aA[p], pe[p+1], wdA[kh*3+2]);
            fma2(aB[p], pe[p],   wdB[kh*3+0]);
            fma2(aB[p], po[p],   wdB[kh*3+1]);
            fma2(aB[p], pe[p+1], wdB[kh*3+2]);
        }
    }
}

template<int OH, int NP>
__device__ __forceinline__ void tmpl_store(float* out, int b, int oc0, int row,
                                           const u64* aA, const u64* aB){
    float scA = g_scale_t[oc0],   biA = g_bias_t[oc0];
    float scB = g_scale_t[oc0+1], biB = g_bias_t[oc0+1];
    float* pA = out + (((size_t)b*C + oc0  )*OH + row)*OH;
    float* pB = out + (((size_t)b*C + oc0+1)*OH + row)*OH;
#pragma unroll
    for (int p = 0; p < NP; p++){
        float2 fa = unpk(aA[p]), fb = unpk(aB[p]);
        int col = 2*p;
        if (col < OH){
            float va = fmaf(scA, fa.x, biA); pA[col] = va > 0.f ? va : 0.f;
            float vb = fmaf(scB, fb.x, biB); pB[col] = vb > 0.f ? vb : 0.f;
        }
        if (col+1 < OH){
            float va = fmaf(scA, fa.y, biA); pA[col+1] = va > 0.f ? va : 0.f;
            float vb = fmaf(scB, fb.y, biB); pB[col+1] = vb > 0.f ? vb : 0.f;
        }
    }
}

__global__ void __launch_bounds__(512) tmpl_all(const float* __restrict__ lin,
                                                const float* __restrict__ min_,
                                                const float* __restrict__ sin_,
                                                const float* __restrict__ w,
                                                float* lo, float* mo, float* so){
    __shared__ __align__(16) float s_in[16*155 + 4];
    __shared__ __align__(16) float s_w[144*66];
    int tid = threadIdx.x;
    int ocp = tid & 31, slot = tid >> 5;
    int b = blockIdx.x, ocbase = blockIdx.y * 64;
    int oc0 = ocbase + ocp*2;

    u64 aA[4] = {0,0,0,0}, aB[4] = {0,0,0,0};

    for (int ic0 = 0; ic0 < C; ic0 += 16){
        __syncthreads();
#pragma unroll 1
        for (int idx = tid; idx < 16*155; idx += 512){
            int ic = idx / 155, r = idx % 155;
            size_t cb = (size_t)b*C + ic0 + ic;
            float v;
            if (r < 81)       v = lin [cb*81 + r];
            else if (r < 130) v = min_[cb*49 + (r-81)];
            else              v = sin_[cb*25 + (r-130)];
            s_in[ic*155 + r] = v;
        }
#pragma unroll 1
        for (int idx = tid; idx < 64*144; idx += 512){
            int oc = idx / 144, r = idx % 144;
            s_w[r*66 + oc] = w[(size_t)(ocbase+oc)*2304 + (size_t)ic0*9 + r];
        }
        __syncthreads();

        if (slot < 7){
            int row = slot;
#pragma unroll 1
            for (int ic = 0; ic < 16; ic++){
                u64 wdA[9], wdB[9];
#pragma unroll
                for (int k = 0; k < 9; k++){
                    u64 pr = *(const u64*)&s_w[(ic*9+k)*66 + ocp*2];
                    float2 f = unpk(pr);
                    wdA[k] = dup2(f.x); wdB[k] = dup2(f.y);
                }
                row3<9,4>(s_in + ic*155 + row*9, wdA, wdB, aA, aB);
            }
        } else if (slot < 12){
            int row = slot - 7;
#pragma unroll 1
            for (int ic = 0; ic < 16; ic++){
                u64 wdA[9], wdB[9];
#pragma unroll
                for (int k = 0; k < 9; k++){
                    u64 pr = *(const u64*)&s_w[(ic*9+k)*66 + ocp*2];
                    float2 f = unpk(pr);
                    wdA[k] = dup2(f.x); wdB[k] = dup2(f.y);
                }
                row3<7,3>(s_in + ic*155 + 81 + row*7, wdA, wdB, aA, aB);
            }
        } else if (slot < 15){
            int row = slot - 12;
#pragma unroll 1
            for (int ic = 0; ic < 16; ic++){
                u64 wdA[9], wdB[9];
#pragma unroll
                for (int k = 0; k < 9; k++){
                    u64 pr = *(const u64*)&s_w[(ic*9+k)*66 + ocp*2];
                    float2 f = unpk(pr);
                    wdA[k] = dup2(f.x); wdB[k] = dup2(f.y);
                }
                row3<5,2>(s_in + ic*155 + 130 + row*5, wdA, wdB, aA, aB);
            }
        }
    }

    if (slot < 7)       tmpl_store<7,4>(lo, b, oc0, slot,      aA, aB);
    else if (slot < 12) tmpl_store<5,3>(mo, b, oc0, slot - 7,  aA, aB);
    else if (slot < 15) tmpl_store<3,2>(so, b, oc0, slot - 12, aA, aB);
}

// ---------------- search conv: fp16-split mma.m16n8k16 + ldmatrix ----------------
#define SA_ROWS 248
#define SA_STRIDE 20
#define SA_N (SA_ROWS*SA_STRIDE)
#define SB_STRIDE 20
#define SB_N (64*SB_STRIDE)
#define CSM_BYTES ((2*SA_N + 2*SB_N) * 4)

#define MMA16(acc, a0,a1,a2,a3, b0,b1) \
    asm volatile( \
        "mma.sync.aligned.m16n8k16.row.col.f32.f16.f16.f32 " \
        "{%0,%1,%2,%3}, {%4,%5,%6,%7}, {%8,%9}, {%0,%1,%2,%3};" \
        : "+f"((acc)[0]), "+f"((acc)[1]), "+f"((acc)[2]), "+f"((acc)[3]) \
        : "r"(a0), "r"(a1), "r"(a2), "r"(a3), "r"(b0), "r"(b1))

#define LDSM4(r0,r1,r2,r3, addr) \
    asm volatile("ldmatrix.sync.aligned.m8n8.x4.shared.b16 {%0,%1,%2,%3}, [%4];" \
        : "=r"(r0), "=r"(r1), "=r"(r2), "=r"(r3) : "r"(addr))

__global__ void __launch_bounds__(256) conv_search_mma(const float* __restrict__ in){
    extern __shared__ __align__(16) u32 smem_dyn[];
    u32* sa_h = smem_dyn;
    u32* sa_l = sa_h + SA_N;
    u32* sb_h = sa_l + SA_N;
    u32* sb_l = sb_h + SB_N;

    int tid = threadIdx.x;
    int lane = tid & 31, wid = tid >> 5;
    int g = lane >> 2, t = lane & 3;
    int wm = wid & 3, wn = wid >> 2;
    int b = blockIdx.x;
    int pstart = blockIdx.y * 128;
    int ocb0 = blockIdx.z * 64;
    int r_first = pstart / 29;

    int pxv[2][2];
    bool pvalid[2][2];
#pragma unroll
    for (int mf = 0; mf < 2; mf++)
#pragma unroll
        for (int h = 0; h < 2; h++){
            int px = pstart + wm*32 + mf*16 + g + h*8;
            pvalid[mf][h] = (px < 841);
            pxv[mf][h] = px < 841 ? px : 840;
        }

    int rrow = ((lane >> 3) & 1) * 8 + (lane & 7);
    int kwA = (lane & 16) ? 4 : 0;
    u32 aoff[2];
#pragma unroll
    for (int mf = 0; mf < 2; mf++){
        int pA = pstart + wm*32 + mf*16 + rrow;
        int pAc = pA < 841 ? pA : 840;
        int rA = pAc / 29, cA = pAc - rA*29;
        int rcA = (rA - r_first)*31 + cA;
        aoff[mf] = (u32)((rcA*SA_STRIDE + kwA) * 4);
    }
    int ocq = ((lane >> 4) & 1) * 8 + (lane & 7);
    int kwB = (lane & 8) ? 4 : 0;
    u32 boff[2];
#pragma unroll
    for (int q = 0; q < 2; q++)
        boff[q] = (u32)(((wn*32 + q*16 + ocq)*SB_STRIDE + kwB) * 4);

    u32 sah_b = smem_u32(sa_h), sal_b = smem_u32(sa_l);
    u32 sbh_b = smem_u32(sb_h), sbl_b = smem_u32(sb_l);

    float acc[2][4][4];
#pragma unroll
    for (int mf = 0; mf < 2; mf++)
#pragma unroll
        for (int nf = 0; nf < 4; nf++)
#pragma unroll
            for (int i = 0; i < 4; i++) acc[mf][nf][i] = 0.f;

    const float* inb = in + (size_t)b * C * 961;

    for (int ic0 = 0; ic0 < C; ic0 += 32){
        __syncthreads();
#pragma unroll 1
        for (int icp = 0; icp < 16; icp++){
            int rc = tid;
            if (rc < SA_ROWS){
                int gidx = r_first*31 + rc;
                int ic = ic0 + icp*2;
                float v0 = 0.f, v1 = 0.f;
                if (gidx < 961){
                    v0 = inb[ic*961 + gidx];
                    v1 = inb[(ic+1)*961 + gidx];
                }
                __half h0 = __float2half_rn(v0), h1 = __float2half_rn(v1);
                float r0 = v0 - __half2float(h0), r1 = v1 - __half2float(h1);
                sa_h[rc*SA_STRIDE + icp] = h2pack(h0, h1);
                sa_l[rc*SA_STRIDE + icp] = h2pack(__float2half_rn(r0), __float2half_rn(r1));
            }
        }
#pragma unroll 1
        for (int khw = 0; khw < 9; khw++){
            __syncthreads();
            {
                const __half* wh = g_wth + ((size_t)khw*C + ocb0)*C + ic0;
                const __half* wl = g_wtl + ((size_t)khw*C + ocb0)*C + ic0;
                int oc = tid >> 2, q4 = tid & 3;
                uint4 vh = *(const uint4*)(wh + (size_t)oc*C + q4*8);
                uint4 vl = *(const uint4*)(wl + (size_t)oc*C + q4*8);
                *(uint4*)(sb_h + oc*SB_STRIDE + q4*4) = vh;
                *(uint4*)(sb_l + oc*SB_STRIDE + q4*4) = vl;
            }
            __syncthreads();
            int kh = khw / 3, kw = khw - kh*3;
            u32 shb = (u32)((kh*31 + kw) * SA_STRIDE * 4);
#pragma unroll
            for (int ks = 0; ks < 2; ks++){
                u32 ksb = ks * 32;
                u32 bh[8], bl[8];
                LDSM4(bh[0], bh[1], bh[2], bh[3], sbh_b + boff[0] + ksb);
                LDSM4(bh[4], bh[5], bh[6], bh[7], sbh_b + boff[1] + ksb);
                LDSM4(bl[0], bl[1], bl[2], bl[3], sbl_b + boff[0] + ksb);
                LDSM4(bl[4], bl[5], bl[6], bl[7], sbl_b + boff[1] + ksb);
#pragma unroll
                for (int mf = 0; mf < 2; mf++){
                    u32 ah[4], al[4];
                    LDSM4(ah[0], ah[1], ah[2], ah[3], sah_b + aoff[mf] + shb + ksb);
                    LDSM4(al[0], al[1], al[2], al[3], sal_b + aoff[mf] + shb + ksb);
#pragma unroll
                    for (int nf = 0; nf < 4; nf++){
                        MMA16(acc[mf][nf], ah[0], ah[1], ah[2], ah[3], bh[nf*2], bh[nf*2+1]);
                        MMA16(acc[mf][nf], ah[0], ah[1], ah[2], ah[3], bl[nf*2], bl[nf*2+1]);
                        MMA16(acc[mf][nf], al[0], al[1], al[2], al[3], bh[nf*2], bh[nf*2+1]);
                    }
                }
            }
        }
    }

    const float inv1024 = 0.0009765625f;
#pragma unroll
    for (int nf = 0; nf < 4; nf++){
        int oc0 = ocb0 + wn*32 + nf*8 + 2*t;
        int oc1 = oc0 + 1;
        float sc0 = g_scale_s[oc0] * inv1024, bi0 = g_bias_s[oc0];
        float sc1 = g_scale_s[oc1] * inv1024, bi1 = g_bias_s[oc1];
#pragma unroll
        for (int mf = 0; mf < 2; mf++){
            if (pvalid[mf][0]){
                float v0 = fmaf(sc0, acc[mf][nf][0], bi0);
                float v1 = fmaf(sc1, acc[mf][nf][1], bi1);
                g_s[((size_t)b*C + oc0)*841 + pxv[mf][0]] = v0 > 0.f ? v0 : 0.f;
                g_s[((size_t)b*C + oc1)*841 + pxv[mf][0]] = v1 > 0.f ? v1 : 0.f;
            }
            if (pvalid[mf][1]){
                float v2 = fmaf(sc0, acc[mf][nf][2], bi0);
                float v3 = fmaf(sc1, acc[mf][nf][3], bi1);
                g_s[((size_t)b*C + oc0)*841 + pxv[mf][1]] = v2 > 0.f ? v2 : 0.f;
                g_s[((size_t)b*C + oc1)*841 + pxv[mf][1]] = v3 > 0.f ? v3 : 0.f;
            }
        }
    }
}

// ---------------- head GEMM via fp16-split mma + ldmatrix ----------------
// block = (b, 128-px tile, 64-n tile). K=256 in 8 chunks. Epilogue: BN+ReLU+*w2,
// reduce over block's 64 n, atomicAdd into g_hp partials.
__global__ void __launch_bounds__(256) head_mma(const float* __restrict__ x, int HW,
                                                const float* __restrict__ w2,
                                                float* __restrict__ hp){
    __shared__ __align__(16) u32 sa_h[128*SA_STRIDE];
    __shared__ __align__(16) u32 sa_l[128*SA_STRIDE];
    __shared__ __align__(16) u32 sb_h[64*SB_STRIDE];
    __shared__ __align__(16) u32 sb_l[64*SB_STRIDE];

    int tid = threadIdx.x;
    int lane = tid & 31, wid = tid >> 5;
    int g = lane >> 2, t = lane & 3;
    int wm = wid & 3, wn = wid >> 2;
    int b = blockIdx.x;
    int px0 = blockIdx.y * 128;
    int nb0 = blockIdx.z * 64;

    int rrow = ((lane >> 3) & 1) * 8 + (lane & 7);
    int kwA = (lane & 16) ? 4 : 0;
    u32 aoff[2];
#pragma unroll
    for (int mf = 0; mf < 2; mf++)
        aoff[mf] = (u32)(((wm*32 + mf*16 + rrow)*SA_STRIDE + kwA) * 4);
    int ocq = ((lane >> 4) & 1) * 8 + (lane & 7);
    int kwB = (lane & 8) ? 4 : 0;
    u32 boff[2];
#pragma unroll
    for (int q = 0; q < 2; q++)
        boff[q] = (u32)(((wn*32 + q*16 + ocq)*SB_STRIDE + kwB) * 4);

    u32 sah_b = smem_u32(sa_h), sal_b = smem_u32(sa_l);
    u32 sbh_b = smem_u32(sb_h), sbl_b = smem_u32(sb_l);

    float acc[2][4][4];
#pragma unroll
    for (int mf = 0; mf < 2; mf++)
#pragma unroll
        for (int nf = 0; nf < 4; nf++)
#pragma unroll
            for (int i = 0; i < 4; i++) acc[mf][nf][i] = 0.f;

    const float* xb = x + (size_t)b * C * HW;

#pragma unroll 1
    for (int kc = 0; kc < 8; kc++){
        __syncthreads();
        // stage A: 128 px rows x 32 k (hi/lo)
        if (tid < 128){
            int px = px0 + tid;
            bool ok = (px < HW);
#pragma unroll
            for (int icp = 0; icp < 16; icp++){
                int k = kc*32 + icp*2;
                float v0 = 0.f, v1 = 0.f;
                if (ok){
                    v0 = xb[k*HW + px];
                    v1 = xb[(k+1)*HW + px];
                }
                __half h0 = __float2half_rn(v0), h1 = __float2half_rn(v1);
                float r0 = v0 - __half2float(h0), r1 = v1 - __half2float(h1);
                sa_h[tid*SA_STRIDE + icp] = h2pack(h0, h1);
                sa_l[tid*SA_STRIDE + icp] = h2pack(__float2half_rn(r0), __float2half_rn(r1));
            }
        }
        // stage B: 64 n x 32 k from pre-split w1 planes
        {
            const __half* wh = g_w1h + (size_t)nb0*C + kc*32;
            const __half* wl = g_w1l + (size_t)nb0*C + kc*32;
            int oc = tid >> 2, q4 = tid & 3;
            uint4 vh = *(const uint4*)(wh + (size_t)oc*C + q4*8);
            uint4 vl = *(const uint4*)(wl + (size_t)oc*C + q4*8);
            *(uint4*)(sb_h + oc*SB_STRIDE + q4*4) = vh;
            *(uint4*)(sb_l + oc*SB_STRIDE + q4*4) = vl;
        }
        __syncthreads();
#pragma unroll
        for (int ks = 0; ks < 2; ks++){
            u32 ksb = ks * 32;
            u32 bh[8], bl[8];
            LDSM4(bh[0], bh[1], bh[2], bh[3], sbh_b + boff[0] + ksb);
            LDSM4(bh[4], bh[5], bh[6], bh[7], sbh_b + boff[1] + ksb);
            LDSM4(bl[0], bl[1], bl[2], bl[3], sbl_b + boff[0] + ksb);
            LDSM4(bl[4], bl[5], bl[6], bl[7], sbl_b + boff[1] + ksb);
#pragma unroll
            for (int mf = 0; mf < 2; mf++){
                u32 ah[4], al[4];
                LDSM4(ah[0], ah[1], ah[2], ah[3], sah_b + aoff[mf] + ksb);
                LDSM4(al[0], al[1], al[2], al[3], sal_b + aoff[mf] + ksb);
#pragma unroll
                for (int nf = 0; nf < 4; nf++){
                    MMA16(acc[mf][nf], ah[0], ah[1], ah[2], ah[3], bh[nf*2], bh[nf*2+1]);
                    MMA16(acc[mf][nf], ah[0], ah[1], ah[2], ah[3], bl[nf*2], bl[nf*2+1]);
                    MMA16(acc[mf][nf], al[0], al[1], al[2], al[3], bh[nf*2], bh[nf*2+1]);
                }
            }
        }
    }

    // epilogue: BN+ReLU, *w2, reduce over this block's 64 n, atomicAdd partials
    const float inv1024 = 0.0009765625f;
    float psum[2][2] = {{0.f,0.f},{0.f,0.f}};
#pragma unroll
    for (int nf = 0; nf < 4; nf++){
        int oc0 = nb0 + wn*32 + nf*8 + 2*t;
        int oc1 = oc0 + 1;
        float s0 = g_scale_1[oc0] * inv1024, b0 = g_bias_1[oc0], w20 = w2[oc0];
        float s1 = g_scale_1[oc1] * inv1024, b1 = g_bias_1[oc1], w21 = w2[oc1];
#pragma unroll
        for (int mf = 0; mf < 2; mf++){
            psum[mf][0] += fmaxf(fmaf(s0, acc[mf][nf][0], b0), 0.f) * w20
                         + fmaxf(fmaf(s1, acc[mf][nf][1], b1), 0.f) * w21;
            psum[mf][1] += fmaxf(fmaf(s0, acc[mf][nf][2], b0), 0.f) * w20
                         + fmaxf(fmaf(s1, acc[mf][nf][3], b1), 0.f) * w21;
        }
    }
#pragma unroll
    for (int mf = 0; mf < 2; mf++)
#pragma unroll
        for (int h = 0; h < 2; h++){
            float v = psum[mf][h];
            v += __shfl_xor_sync(0xffffffffu, v, 1);
            v += __shfl_xor_sync(0xffffffffu, v, 2);
            int px = px0 + wm*32 + mf*16 + g + h*8;
            if (t == 0 && px < HW)
                atomicAdd(&hp[(size_t)b*HW + px], v);
        }
}

// ---------------- corr v2: warp = channel, lane = output row, f32x2 --------------
template<int TS, int PAD, int OS>
__global__ void __launch_bounds__(256) corr_v2(const float* __restrict__ t,
                                               float* __restrict__ out){
    constexpr int R = OS + TS - 1;
    constexpr int STRIDE = 35;
    constexpr int NPAIR = (OS + 1) / 2;
    constexpr int VW = 2*NPAIR + TS - 1;
    constexpr int NPE = VW / 2;
    __shared__ float s_pad[8 * R * STRIDE];
    __shared__ float s_t[8 * TS * TS];
    int tid = threadIdx.x;
    int wrp = tid >> 5, lane = tid & 31;
    int b = blockIdx.x;
    int c0 = blockIdx.y * 8;

#pragma unroll 1
    for (int idx = tid; idx < 8 * R * STRIDE; idx += 256) s_pad[idx] = 0.f;
    __syncthreads();
    const float* sb = g_s + ((size_t)b*C + c0) * 841;
#pragma unroll 1
    for (int idx = tid; idx < 8 * 841; idx += 256){
        int ch = idx / 841, rem = idx - ch*841;
        int row = rem / 29, col = rem - row*29;
        s_pad[ch*R*STRIDE + (row + PAD)*STRIDE + col + PAD] = sb[ch*841 + rem];
    }
    const float* tb = t + ((size_t)b*C + c0) * TS * TS;
#pragma unroll 1
    for (int idx = tid; idx < 8 * TS * TS; idx += 256) s_t[idx] = tb[idx];
    __syncthreads();

    if (lane < OS){
        const float* sp = s_pad + wrp*R*STRIDE + lane*STRIDE;
        const float* tp = s_t + wrp*TS*TS;
        u64 a[NPAIR];
#pragma unroll
        for (int p = 0; p < NPAIR; p++) a[p] = 0ull;
#pragma unroll
        for (int trow = 0; trow < TS; trow++){
            u64 wd[TS];
#pragma unroll
            for (int j = 0; j < TS; j++) wd[j] = dup2(tp[trow*TS + j]);
            float v[VW];
#pragma unroll
            for (int k = 0; k < VW; k++) v[k] = sp[trow*STRIDE + k];
            u64 pe[NPE], po[NPE-1];
#pragma unroll
            for (int k = 0; k < NPE; k++) pe[k] = pack2(v[2*k], v[2*k+1]);
#pragma unroll
            for (int k = 0; k < NPE-1; k++) po[k] = pack2(v[2*k+1], v[2*k+2]);
#pragma unroll
            for (int j = 0; j < TS; j++){
                if (j & 1){
#pragma unroll
                    for (int p = 0; p < NPAIR; p++) fma2(a[p], po[p + (j>>1)], wd[j]);
                } else {
#pragma unroll
                    for (int p = 0; p < NPAIR; p++) fma2(a[p], pe[p + (j>>1)], wd[j]);
                }
            }
        }
        float* op = out + (((size_t)b*C + c0 + wrp)*OS + lane)*OS;
#pragma unroll
        for (int p = 0; p < NPAIR; p++){
            float2 f = unpk(a[p]);
            op[2*p] = f.x;
            if (2*p + 1 < OS) op[2*p + 1] = f.y;
        }
    }
}

// ---------------- launch ----------------
extern "C" void kernel_launch(void* const* d_in, const int* in_sizes, int n_in,
                              void* d_out, int out_size){
    const float* large  = (const float*)d_in[0];
    const float* medium = (const float*)d_in[1];
    const float* small  = (const float*)d_in[2];
    const float* search = (const float*)d_in[3];
    const float* wt  = (const float*)d_in[4];
    const float* bt  = (const float*)d_in[5];
    const float* gt  = (const float*)d_in[6];
    const float* bet = (const float*)d_in[7];
    const float* mt  = (const float*)d_in[8];
    const float* vt  = (const float*)d_in[9];
    const float* ws  = (const float*)d_in[10];
    const float* bs  = (const float*)d_in[11];
    const float* gs  = (const float*)d_in[12];
    const float* bes = (const float*)d_in[13];
    const float* ms  = (const float*)d_in[14];
    const float* vs  = (const float*)d_in[15];
    const float* w1  = (const float*)d_in[16];
    const float* b1  = (const float*)d_in[17];
    const float* g1  = (const float*)d_in[18];
    const float* be1 = (const float*)d_in[19];
    const float* m1  = (const float*)d_in[20];
    const float* v1  = (const float*)d_in[21];
    const float* w2  = (const float*)d_in[22];
    const float* b2  = (const float*)d_in[23];
    float* out = (float*)d_out;

    float *lf, *mf, *sf, *lc, *mc, *sc, *hp;
    cudaGetSymbolAddress((void**)&lf, g_lf);
    cudaGetSymbolAddress((void**)&mf, g_mf);
    cudaGetSymbolAddress((void**)&sf, g_sf);
    cudaGetSymbolAddress((void**)&lc, g_lc);
    cudaGetSymbolAddress((void**)&mc, g_mc);
    cudaGetSymbolAddress((void**)&sc, g_sc);
    cudaGetSymbolAddress((void**)&hp, g_hp);

    static cudaStream_t st1 = 0, st2 = 0;
    static cudaEvent_t evRoot = 0, evT = 0, evFork = 0, ev1 = 0, ev2 = 0;
    if (!st1){
        cudaStreamCreateWithFlags(&st1, cudaStreamNonBlocking);
        cudaStreamCreateWithFlags(&st2, cudaStreamNonBlocking);
        cudaEventCreateWithFlags(&evRoot, cudaEventDisableTiming);
        cudaEventCreateWithFlags(&evT, cudaEventDisableTiming);
        cudaEventCreateWithFlags(&evFork, cudaEventDisableTiming);
        cudaEventCreateWithFlags(&ev1, cudaEventDisableTiming);
        cudaEventCreateWithFlags(&ev2, cudaEventDisableTiming);
        cudaFuncSetAttribute(conv_search_mma,
                             cudaFuncAttributeMaxDynamicSharedMemorySize, CSM_BYTES);
    }

    prep_kernel<<<1, 256>>>(bt, gt, bet, mt, vt, bs, gs, bes, ms, vs, b1, g1, be1, m1, v1);

    // fork: tmpl_all runs on st1 concurrently with wt_trans + conv on stream 0
    cudaEventRecord(evRoot, 0);
    cudaStreamWaitEvent(st1, evRoot, 0);
    tmpl_all<<<dim3(64, 4), 512, 0, st1>>>(large, medium, small, wt, lf, mf, sf);
    cudaEventRecord(evT, st1);

    wt_trans<<<(9*C*C + 255)/256, 256>>>(ws);
    w1_split<<<(C*C + 255)/256, 256>>>(w1);
    zero_hp<<<(HP_TOTAL + 255)/256, 256>>>();
    conv_search_mma<<<dim3(64, 7, 4), 256, CSM_BYTES>>>(search);
    cudaStreamWaitEvent(0, evT, 0);

    // fork three independent corr->head chains
    cudaEventRecord(evFork, 0);
    cudaStreamWaitEvent(st1, evFork, 0);
    cudaStreamWaitEvent(st2, evFork, 0);

    float* hp_l = hp;
    float* hp_m = hp + 64*729;
    float* hp_s = hp + 64*729 + 64*625;

    corr_v2<7, 2, 27><<<dim3(64, 32), 256>>>(lf, lc);
    head_mma<<<dim3(64, 6, 4), 256>>>(lc, 729, w2, hp_l);

    corr_v2<5, 0, 25><<<dim3(64, 32), 256, 0, st1>>>(mf, mc);
    head_mma<<<dim3(64, 5, 4), 256, 0, st1>>>(mc, 625, w2, hp_m);
    cudaEventRecord(ev1, st1);

    corr_v2<3, 0, 27><<<dim3(64, 32), 256, 0, st2>>>(sf, sc);
    head_mma<<<dim3(64, 6, 4), 256, 0, st2>>>(sc, 729, w2, hp_s);
    cudaEventRecord(ev2, st2);

    cudaStreamWaitEvent(0, ev1, 0);
    cudaStreamWaitEvent(0, ev2, 0);
    final_sig<<<(HP_TOTAL + 255)/256, 256>>>(b2, out);
}

// round 17
// speedup vs baseline: 1.7274x; 1.0251x over previous
#include <cuda_runtime.h>
#include <cuda_fp16.h>
#include <math.h>

#define B 64
#define C 256
#define HP_TOTAL (64*(729+625+729))

typedef unsigned long long u64;
typedef unsigned int u32;

__device__ __forceinline__ u64 pack2(float lo, float hi){
    u64 r; asm("mov.b64 %0, {%1, %2};" : "=l"(r) : "f"(lo), "f"(hi)); return r;
}
__device__ __forceinline__ u64 dup2(float v){
    u64 r; asm("mov.b64 %0, {%1, %1};" : "=l"(r) : "f"(v)); return r;
}
__device__ __forceinline__ void fma2(u64 &d, u64 a, u64 b){
    asm("fma.rn.f32x2 %0, %1, %2, %0;" : "+l"(d) : "l"(a), "l"(b));
}
__device__ __forceinline__ u64 add2(u64 a, u64 b){
    u64 d; asm("add.rn.f32x2 %0, %1, %2;" : "=l"(d) : "l"(a), "l"(b)); return d;
}
__device__ __forceinline__ float2 unpk(u64 v){
    float2 f; asm("mov.b64 {%0, %1}, %2;" : "=f"(f.x), "=f"(f.y) : "l"(v)); return f;
}
__device__ __forceinline__ u32 h2pack(__half a, __half b){
    return ((u32)__half_as_ushort(b) << 16) | (u32)__half_as_ushort(a);
}
__device__ __forceinline__ u32 smem_u32(const void* p){
    u32 a; asm("{ .reg .u64 t; cvta.to.shared.u64 t, %1; cvt.u32.u64 %0, t; }" : "=r"(a) : "l"(p));
    return a;
}

// ---------------- scratch ----------------
__device__ float g_lf[B*C*7*7];
__device__ float g_mf[B*C*5*5];
__device__ float g_sf[B*C*3*3];
__device__ float g_s [B*C*29*29];
__device__ float g_lc[B*C*27*27];
__device__ float g_mc[B*C*25*25];
__device__ float g_sc[B*C*27*27];
__device__ float g_hp[HP_TOTAL];
__device__ __align__(16) __half g_wth[9*C*C];
__device__ __align__(16) __half g_wtl[9*C*C];
__device__ __align__(16) __half g_w1h[C*C];
__device__ __align__(16) __half g_w1l[C*C];
__device__ float g_scale_t[C], g_bias_t[C];
__device__ float g_scale_s[C], g_bias_s[C];
__device__ float g_scale_1[C], g_bias_1[C];

__global__ void prep_kernel(const float* bt,const float* gt,const float* bet,const float* mt,const float* vt,
                            const float* bs,const float* gs,const float* bes,const float* ms,const float* vs,
                            const float* b1,const float* g1,const float* be1,const float* m1,const float* v1){
    int c = threadIdx.x;
    { float inv = gt[c]*rsqrtf(vt[c]+1e-5f); g_scale_t[c]=inv; g_bias_t[c]=bt[c]*inv + bet[c] - mt[c]*inv; }
    { float inv = gs[c]*rsqrtf(vs[c]+1e-5f); g_scale_s[c]=inv; g_bias_s[c]=bs[c]*inv + bes[c] - ms[c]*inv; }
    { float inv = g1[c]*rsqrtf(v1[c]+1e-5f); g_scale_1[c]=inv; g_bias_1[c]=b1[c]*inv + be1[c] - m1[c]*inv; }
}

__global__ void wt_trans(const float* __restrict__ w){
    int idx = blockIdx.x * 256 + threadIdx.x;
    if (idx < 9*C*C){
        int khw = idx % 9;
        int rest = idx / 9;
        int ic = rest & 255;
        int oc = rest >> 8;
        float v = w[idx] * 1024.0f;
        __half h = __float2half_rn(v);
        size_t o = ((size_t)khw*C + oc)*C + ic;
        g_wth[o] = h;
        g_wtl[o] = __float2half_rn(v - __half2float(h));
    }
}

__global__ void w1_split(const float* __restrict__ w1){
    int idx = blockIdx.x * 256 + threadIdx.x;
    if (idx < C*C){
        float v = w1[idx] * 1024.0f;
        __half h = __float2half_rn(v);
        g_w1h[idx] = h;
        g_w1l[idx] = __float2half_rn(v - __half2float(h));
    }
}

__global__ void zero_hp(){
    int i = blockIdx.x * 256 + threadIdx.x;
    if (i < HP_TOTAL) g_hp[i] = 0.f;
}

__global__ void final_sig(const float* __restrict__ b2, float* __restrict__ out){
    int i = blockIdx.x * 256 + threadIdx.x;
    if (i < HP_TOTAL) out[i] = 1.f / (1.f + expf(-(g_hp[i] + b2[0])));
}

// ---------------- merged template conv 3x3 + BN + ReLU, f32x2 ----------------
template<int W, int NP>
__device__ __forceinline__ void row3(const float* ip, const u64* wdA, const u64* wdB,
                                     u64* aA, u64* aB){
#pragma unroll
    for (int kh = 0; kh < 3; kh++){
        float rv[2*NP+2];
#pragma unroll
        for (int j = 0; j < 2*NP+2; j++) rv[j] = ip[kh*W + j];
        u64 pe[NP+1], po[NP];
#pragma unroll
        for (int p = 0; p <= NP; p++) pe[p] = pack2(rv[2*p], rv[2*p+1]);
#pragma unroll
        for (int p = 0; p < NP; p++) po[p] = pack2(rv[2*p+1], rv[2*p+2]);
#pragma unroll
        for (int p = 0; p < NP; p++){
            fma2(aA[p], pe[p],   wdA[kh*3+0]);
            fma2(aA[p], po[p],   wdA[kh*3+1]);
            fma2(aA[p], pe[p+1], wdA[kh*3+2]);
            fma2(aB[p], pe[p],   wdB[kh*3+0]);
            fma2(aB[p], po[p],   wdB[kh*3+1]);
            fma2(aB[p], pe[p+1], wdB[kh*3+2]);
        }
    }
}

template<int OH, int NP>
__device__ __forceinline__ void tmpl_store(float* out, int b, int oc0, int row,
                                           const u64* aA, const u64* aB){
    float scA = g_scale_t[oc0],   biA = g_bias_t[oc0];
    float scB = g_scale_t[oc0+1], biB = g_bias_t[oc0+1];
    float* pA = out + (((size_t)b*C + oc0  )*OH + row)*OH;
    float* pB = out + (((size_t)b*C + oc0+1)*OH + row)*OH;
#pragma unroll
    for (int p = 0; p < NP; p++){
        float2 fa = unpk(aA[p]), fb = unpk(aB[p]);
        int col = 2*p;
        if (col < OH){
            float va = fmaf(scA, fa.x, biA); pA[col] = va > 0.f ? va : 0.f;
            float vb = fmaf(scB, fb.x, biB); pB[col] = vb > 0.f ? vb : 0.f;
        }
        if (col+1 < OH){
            float va = fmaf(scA, fa.y, biA); pA[col+1] = va > 0.f ? va : 0.f;
            float vb = fmaf(scB, fb.y, biB); pB[col+1] = vb > 0.f ? vb : 0.f;
        }
    }
}

__global__ void __launch_bounds__(512) tmpl_all(const float* __restrict__ lin,
                                                const float* __restrict__ min_,
                                                const float* __restrict__ sin_,
                                                const float* __restrict__ w,
                                                float* lo, float* mo, float* so){
    __shared__ __align__(16) float s_in[16*155 + 4];
    __shared__ __align__(16) float s_w[144*66];
    int tid = threadIdx.x;
    int ocp = tid & 31, slot = tid >> 5;
    int b = blockIdx.x, ocbase = blockIdx.y * 64;
    int oc0 = ocbase + ocp*2;

    u64 aA[4] = {0,0,0,0}, aB[4] = {0,0,0,0};

    for (int ic0 = 0; ic0 < C; ic0 += 16){
        __syncthreads();
#pragma unroll 1
        for (int idx = tid; idx < 16*155; idx += 512){
            int ic = idx / 155, r = idx % 155;
            size_t cb = (size_t)b*C + ic0 + ic;
            float v;
            if (r < 81)       v = lin [cb*81 + r];
            else if (r < 130) v = min_[cb*49 + (r-81)];
            else              v = sin_[cb*25 + (r-130)];
            s_in[ic*155 + r] = v;
        }
#pragma unroll 1
        for (int idx = tid; idx < 64*144; idx += 512){
            int oc = idx / 144, r = idx % 144;
            s_w[r*66 + oc] = w[(size_t)(ocbase+oc)*2304 + (size_t)ic0*9 + r];
        }
        __syncthreads();

        if (slot < 7){
            int row = slot;
#pragma unroll 1
            for (int ic = 0; ic < 16; ic++){
                u64 wdA[9], wdB[9];
#pragma unroll
                for (int k = 0; k < 9; k++){
                    u64 pr = *(const u64*)&s_w[(ic*9+k)*66 + ocp*2];
                    float2 f = unpk(pr);
                    wdA[k] = dup2(f.x); wdB[k] = dup2(f.y);
                }
                row3<9,4>(s_in + ic*155 + row*9, wdA, wdB, aA, aB);
            }
        } else if (slot < 12){
            int row = slot - 7;
#pragma unroll 1
            for (int ic = 0; ic < 16; ic++){
                u64 wdA[9], wdB[9];
#pragma unroll
                for (int k = 0; k < 9; k++){
                    u64 pr = *(const u64*)&s_w[(ic*9+k)*66 + ocp*2];
                    float2 f = unpk(pr);
                    wdA[k] = dup2(f.x); wdB[k] = dup2(f.y);
                }
                row3<7,3>(s_in + ic*155 + 81 + row*7, wdA, wdB, aA, aB);
            }
        } else if (slot < 15){
            int row = slot - 12;
#pragma unroll 1
            for (int ic = 0; ic < 16; ic++){
                u64 wdA[9], wdB[9];
#pragma unroll
                for (int k = 0; k < 9; k++){
                    u64 pr = *(const u64*)&s_w[(ic*9+k)*66 + ocp*2];
                    float2 f = unpk(pr);
                    wdA[k] = dup2(f.x); wdB[k] = dup2(f.y);
                }
                row3<5,2>(s_in + ic*155 + 130 + row*5, wdA, wdB, aA, aB);
            }
        }
    }

    if (slot < 7)       tmpl_store<7,4>(lo, b, oc0, slot,      aA, aB);
    else if (slot < 12) tmpl_store<5,3>(mo, b, oc0, slot - 7,  aA, aB);
    else if (slot < 15) tmpl_store<3,2>(so, b, oc0, slot - 12, aA, aB);
}

// ---------------- search conv: fp16-split mma + ldmatrix, kh-row B staging -------
#define SA_ROWS 248
#define SA_STRIDE 20
#define SA_N (SA_ROWS*SA_STRIDE)
#define SB_STRIDE 20
#define SB_N (64*SB_STRIDE)
#define CSM_BYTES ((2*SA_N + 6*SB_N) * 4)

#define MMA16(acc, a0,a1,a2,a3, b0,b1) \
    asm volatile( \
        "mma.sync.aligned.m16n8k16.row.col.f32.f16.f16.f32 " \
        "{%0,%1,%2,%3}, {%4,%5,%6,%7}, {%8,%9}, {%0,%1,%2,%3};" \
        : "+f"((acc)[0]), "+f"((acc)[1]), "+f"((acc)[2]), "+f"((acc)[3]) \
        : "r"(a0), "r"(a1), "r"(a2), "r"(a3), "r"(b0), "r"(b1))

#define LDSM4(r0,r1,r2,r3, addr) \
    asm volatile("ldmatrix.sync.aligned.m8n8.x4.shared.b16 {%0,%1,%2,%3}, [%4];" \
        : "=r"(r0), "=r"(r1), "=r"(r2), "=r"(r3) : "r"(addr))

__global__ void __launch_bounds__(256) conv_search_mma(const float* __restrict__ in){
    extern __shared__ __align__(16) u32 smem_dyn[];
    u32* sa_h = smem_dyn;
    u32* sa_l = sa_h + SA_N;
    u32* sb_h = sa_l + SA_N;          // [3 kw][64 oc x SB_STRIDE]
    u32* sb_l = sb_h + 3*SB_N;

    int tid = threadIdx.x;
    int lane = tid & 31, wid = tid >> 5;
    int g = lane >> 2, t = lane & 3;
    int wm = wid & 3, wn = wid >> 2;
    int b = blockIdx.x;
    int pstart = blockIdx.y * 128;
    int ocb0 = blockIdx.z * 64;
    int r_first = pstart / 29;

    int pxv[2][2];
    bool pvalid[2][2];
#pragma unroll
    for (int mf = 0; mf < 2; mf++)
#pragma unroll
        for (int h = 0; h < 2; h++){
            int px = pstart + wm*32 + mf*16 + g + h*8;
            pvalid[mf][h] = (px < 841);
            pxv[mf][h] = px < 841 ? px : 840;
        }

    int rrow = ((lane >> 3) & 1) * 8 + (lane & 7);
    int kwA = (lane & 16) ? 4 : 0;
    u32 aoff[2];
#pragma unroll
    for (int mf = 0; mf < 2; mf++){
        int pA = pstart + wm*32 + mf*16 + rrow;
        int pAc = pA < 841 ? pA : 840;
        int rA = pAc / 29, cA = pAc - rA*29;
        int rcA = (rA - r_first)*31 + cA;
        aoff[mf] = (u32)((rcA*SA_STRIDE + kwA) * 4);
    }
    int ocq = ((lane >> 4) & 1) * 8 + (lane & 7);
    int kwB = (lane & 8) ? 4 : 0;
    u32 boff[2];
#pragma unroll
    for (int q = 0; q < 2; q++)
        boff[q] = (u32)(((wn*32 + q*16 + ocq)*SB_STRIDE + kwB) * 4);

    u32 sah_b = smem_u32(sa_h), sal_b = smem_u32(sa_l);
    u32 sbh_b = smem_u32(sb_h), sbl_b = smem_u32(sb_l);

    float acc[2][4][4];
#pragma unroll
    for (int mf = 0; mf < 2; mf++)
#pragma unroll
        for (int nf = 0; nf < 4; nf++)
#pragma unroll
            for (int i = 0; i < 4; i++) acc[mf][nf][i] = 0.f;

    const float* inb = in + (size_t)b * C * 961;

    for (int ic0 = 0; ic0 < C; ic0 += 32){
        __syncthreads();
        // stage A (hi/lo fp16x2, 16 u32 per row = 32 ic)
#pragma unroll 1
        for (int icp = 0; icp < 16; icp++){
            int rc = tid;
            if (rc < SA_ROWS){
                int gidx = r_first*31 + rc;
                int ic = ic0 + icp*2;
                float v0 = 0.f, v1 = 0.f;
                if (gidx < 961){
                    v0 = inb[ic*961 + gidx];
                    v1 = inb[(ic+1)*961 + gidx];
                }
                __half h0 = __float2half_rn(v0), h1 = __float2half_rn(v1);
                float r0 = v0 - __half2float(h0), r1 = v1 - __half2float(h1);
                sa_h[rc*SA_STRIDE + icp] = h2pack(h0, h1);
                sa_l[rc*SA_STRIDE + icp] = h2pack(__float2half_rn(r0), __float2half_rn(r1));
            }
        }
#pragma unroll 1
        for (int kh = 0; kh < 3; kh++){
            __syncthreads();
            // stage B for all 3 kw of this kh (one barrier pair per kh row)
            {
                int oc = tid >> 2, q4 = tid & 3;
#pragma unroll
                for (int kw = 0; kw < 3; kw++){
                    int khw = kh*3 + kw;
                    const __half* wh = g_wth + ((size_t)khw*C + ocb0)*C + ic0;
                    const __half* wl = g_wtl + ((size_t)khw*C + ocb0)*C + ic0;
                    uint4 vh = *(const uint4*)(wh + (size_t)oc*C + q4*8);
                    uint4 vl = *(const uint4*)(wl + (size_t)oc*C + q4*8);
                    *(uint4*)(sb_h + kw*SB_N + oc*SB_STRIDE + q4*4) = vh;
                    *(uint4*)(sb_l + kw*SB_N + oc*SB_STRIDE + q4*4) = vl;
                }
            }
            __syncthreads();
#pragma unroll
            for (int kw = 0; kw < 3; kw++){
                u32 shb = (u32)((kh*31 + kw) * SA_STRIDE * 4);
                u32 bb = (u32)(kw * SB_N * 4);
#pragma unroll
                for (int ks = 0; ks < 2; ks++){
                    u32 ksb = ks * 32;
                    u32 bh[8], bl[8];
                    LDSM4(bh[0], bh[1], bh[2], bh[3], sbh_b + bb + boff[0] + ksb);
                    LDSM4(bh[4], bh[5], bh[6], bh[7], sbh_b + bb + boff[1] + ksb);
                    LDSM4(bl[0], bl[1], bl[2], bl[3], sbl_b + bb + boff[0] + ksb);
                    LDSM4(bl[4], bl[5], bl[6], bl[7], sbl_b + bb + boff[1] + ksb);
#pragma unroll
                    for (int mf = 0; mf < 2; mf++){
                        u32 ah[4], al[4];
                        LDSM4(ah[0], ah[1], ah[2], ah[3], sah_b + aoff[mf] + shb + ksb);
                        LDSM4(al[0], al[1], al[2], al[3], sal_b + aoff[mf] + shb + ksb);
#pragma unroll
                        for (int nf = 0; nf < 4; nf++){
                            MMA16(acc[mf][nf], ah[0], ah[1], ah[2], ah[3], bh[nf*2], bh[nf*2+1]);
                            MMA16(acc[mf][nf], ah[0], ah[1], ah[2], ah[3], bl[nf*2], bl[nf*2+1]);
                            MMA16(acc[mf][nf], al[0], al[1], al[2], al[3], bh[nf*2], bh[nf*2+1]);
                        }
                    }
                }
            }
        }
    }

    const float inv1024 = 0.0009765625f;
#pragma unroll
    for (int nf = 0; nf < 4; nf++){
        int oc0 = ocb0 + wn*32 + nf*8 + 2*t;
        int oc1 = oc0 + 1;
        float sc0 = g_scale_s[oc0] * inv1024, bi0 = g_bias_s[oc0];
        float sc1 = g_scale_s[oc1] * inv1024, bi1 = g_bias_s[oc1];
#pragma unroll
        for (int mf = 0; mf < 2; mf++){
            if (pvalid[mf][0]){
                float v0 = fmaf(sc0, acc[mf][nf][0], bi0);
                float v1 = fmaf(sc1, acc[mf][nf][1], bi1);
                g_s[((size_t)b*C + oc0)*841 + pxv[mf][0]] = v0 > 0.f ? v0 : 0.f;
                g_s[((size_t)b*C + oc1)*841 + pxv[mf][0]] = v1 > 0.f ? v1 : 0.f;
            }
            if (pvalid[mf][1]){
                float v2 = fmaf(sc0, acc[mf][nf][2], bi0);
                float v3 = fmaf(sc1, acc[mf][nf][3], bi1);
                g_s[((size_t)b*C + oc0)*841 + pxv[mf][1]] = v2 > 0.f ? v2 : 0.f;
                g_s[((size_t)b*C + oc1)*841 + pxv[mf][1]] = v3 > 0.f ? v3 : 0.f;
            }
        }
    }
}

// ---------------- head GEMM via fp16-split mma + ldmatrix ----------------
__global__ void __launch_bounds__(256) head_mma(const float* __restrict__ x, int HW,
                                                const float* __restrict__ w2,
                                                float* __restrict__ hp){
    __shared__ __align__(16) u32 sa_h[128*SA_STRIDE];
    __shared__ __align__(16) u32 sa_l[128*SA_STRIDE];
    __shared__ __align__(16) u32 sb_h[64*SB_STRIDE];
    __shared__ __align__(16) u32 sb_l[64*SB_STRIDE];

    int tid = threadIdx.x;
    int lane = tid & 31, wid = tid >> 5;
    int g = lane >> 2, t = lane & 3;
    int wm = wid & 3, wn = wid >> 2;
    int b = blockIdx.x;
    int px0 = blockIdx.y * 128;
    int nb0 = blockIdx.z * 64;

    int rrow = ((lane >> 3) & 1) * 8 + (lane & 7);
    int kwA = (lane & 16) ? 4 : 0;
    u32 aoff[2];
#pragma unroll
    for (int mf = 0; mf < 2; mf++)
        aoff[mf] = (u32)(((wm*32 + mf*16 + rrow)*SA_STRIDE + kwA) * 4);
    int ocq = ((lane >> 4) & 1) * 8 + (lane & 7);
    int kwB = (lane & 8) ? 4 : 0;
    u32 boff[2];
#pragma unroll
    for (int q = 0; q < 2; q++)
        boff[q] = (u32)(((wn*32 + q*16 + ocq)*SB_STRIDE + kwB) * 4);

    u32 sah_b = smem_u32(sa_h), sal_b = smem_u32(sa_l);
    u32 sbh_b = smem_u32(sb_h), sbl_b = smem_u32(sb_l);

    float acc[2][4][4];
#pragma unroll
    for (int mf = 0; mf < 2; mf++)
#pragma unroll
        for (int nf = 0; nf < 4; nf++)
#pragma unroll
            for (int i = 0; i < 4; i++) acc[mf][nf][i] = 0.f;

    const float* xb = x + (size_t)b * C * HW;

#pragma unroll 1
    for (int kc = 0; kc < 8; kc++){
        __syncthreads();
        {
            int pxl = tid & 127;
            int half = tid >> 7;
            int px = px0 + pxl;
            bool ok = (px < HW);
#pragma unroll
            for (int ii = 0; ii < 8; ii++){
                int icp = half*8 + ii;
                int k = kc*32 + icp*2;
                float v0 = 0.f, v1 = 0.f;
                if (ok){
                    v0 = xb[k*HW + px];
                    v1 = xb[(k+1)*HW + px];
                }
                __half h0 = __float2half_rn(v0), h1 = __float2half_rn(v1);
                float r0 = v0 - __half2float(h0), r1 = v1 - __half2float(h1);
                sa_h[pxl*SA_STRIDE + icp] = h2pack(h0, h1);
                sa_l[pxl*SA_STRIDE + icp] = h2pack(__float2half_rn(r0), __float2half_rn(r1));
            }
        }
        {
            const __half* wh = g_w1h + (size_t)nb0*C + kc*32;
            const __half* wl = g_w1l + (size_t)nb0*C + kc*32;
            int oc = tid >> 2, q4 = tid & 3;
            uint4 vh = *(const uint4*)(wh + (size_t)oc*C + q4*8);
            uint4 vl = *(const uint4*)(wl + (size_t)oc*C + q4*8);
            *(uint4*)(sb_h + oc*SB_STRIDE + q4*4) = vh;
            *(uint4*)(sb_l + oc*SB_STRIDE + q4*4) = vl;
        }
        __syncthreads();
#pragma unroll
        for (int ks = 0; ks < 2; ks++){
            u32 ksb = ks * 32;
            u32 bh[8], bl[8];
            LDSM4(bh[0], bh[1], bh[2], bh[3], sbh_b + boff[0] + ksb);
            LDSM4(bh[4], bh[5], bh[6], bh[7], sbh_b + boff[1] + ksb);
            LDSM4(bl[0], bl[1], bl[2], bl[3], sbl_b + boff[0] + ksb);
            LDSM4(bl[4], bl[5], bl[6], bl[7], sbl_b + boff[1] + ksb);
#pragma unroll
            for (int mf = 0; mf < 2; mf++){
                u32 ah[4], al[4];
                LDSM4(ah[0], ah[1], ah[2], ah[3], sah_b + aoff[mf] + ksb);
                LDSM4(al[0], al[1], al[2], al[3], sal_b + aoff[mf] + ksb);
#pragma unroll
                for (int nf = 0; nf < 4; nf++){
                    MMA16(acc[mf][nf], ah[0], ah[1], ah[2], ah[3], bh[nf*2], bh[nf*2+1]);
                    MMA16(acc[mf][nf], ah[0], ah[1], ah[2], ah[3], bl[nf*2], bl[nf*2+1]);
                    MMA16(acc[mf][nf], al[0], al[1], al[2], al[3], bh[nf*2], bh[nf*2+1]);
                }
            }
        }
    }

    const float inv1024 = 0.0009765625f;
    float psum[2][2] = {{0.f,0.f},{0.f,0.f}};
#pragma unroll
    for (int nf = 0; nf < 4; nf++){
        int oc0 = nb0 + wn*32 + nf*8 + 2*t;
        int oc1 = oc0 + 1;
        float s0 = g_scale_1[oc0] * inv1024, b0 = g_bias_1[oc0], w20 = w2[oc0];
        float s1 = g_scale_1[oc1] * inv1024, b1 = g_bias_1[oc1], w21 = w2[oc1];
#pragma unroll
        for (int mf = 0; mf < 2; mf++){
            psum[mf][0] += fmaxf(fmaf(s0, acc[mf][nf][0], b0), 0.f) * w20
                         + fmaxf(fmaf(s1, acc[mf][nf][1], b1), 0.f) * w21;
            psum[mf][1] += fmaxf(fmaf(s0, acc[mf][nf][2], b0), 0.f) * w20
                         + fmaxf(fmaf(s1, acc[mf][nf][3], b1), 0.f) * w21;
        }
    }
#pragma unroll
    for (int mf = 0; mf < 2; mf++)
#pragma unroll
        for (int h = 0; h < 2; h++){
            float v = psum[mf][h];
            v += __shfl_xor_sync(0xffffffffu, v, 1);
            v += __shfl_xor_sync(0xffffffffu, v, 2);
            int px = px0 + wm*32 + mf*16 + g + h*8;
            if (t == 0 && px < HW)
                atomicAdd(&hp[(size_t)b*HW + px], v);
        }
}

// ---------------- corr v2 ----------------
template<int TS, int PAD, int OS>
__global__ void __launch_bounds__(256) corr_v2(const float* __restrict__ t,
                                               float* __restrict__ out){
    constexpr int R = OS + TS - 1;
    constexpr int STRIDE = 35;
    constexpr int NPAIR = (OS + 1) / 2;
    constexpr int VW = 2*NPAIR + TS - 1;
    constexpr int NPE = VW / 2;
    __shared__ float s_pad[8 * R * STRIDE];
    __shared__ float s_t[8 * TS * TS];
    int tid = threadIdx.x;
    int wrp = tid >> 5, lane = tid & 31;
    int b = blockIdx.x;
    int c0 = blockIdx.y * 8;

#pragma unroll 1
    for (int idx = tid; idx < 8 * R * STRIDE; idx += 256) s_pad[idx] = 0.f;
    __syncthreads();
    const float* sb = g_s + ((size_t)b*C + c0) * 841;
#pragma unroll 1
    for (int idx = tid; idx < 8 * 841; idx += 256){
        int ch = idx / 841, rem = idx - ch*841;
        int row = rem / 29, col = rem - row*29;
        s_pad[ch*R*STRIDE + (row + PAD)*STRIDE + col + PAD] = sb[ch*841 + rem];
    }
    const float* tb = t + ((size_t)b*C + c0) * TS * TS;
#pragma unroll 1
    for (int idx = tid; idx < 8 * TS * TS; idx += 256) s_t[idx] = tb[idx];
    __syncthreads();

    if (lane < OS){
        const float* sp = s_pad + wrp*R*STRIDE + lane*STRIDE;
        const float* tp = s_t + wrp*TS*TS;
        u64 a[NPAIR];
#pragma unroll
        for (int p = 0; p < NPAIR; p++) a[p] = 0ull;
#pragma unroll
        for (int trow = 0; trow < TS; trow++){
            u64 wd[TS];
#pragma unroll
            for (int j = 0; j < TS; j++) wd[j] = dup2(tp[trow*TS + j]);
            float v[VW];
#pragma unroll
            for (int k = 0; k < VW; k++) v[k] = sp[trow*STRIDE + k];
            u64 pe[NPE], po[NPE-1];
#pragma unroll
            for (int k = 0; k < NPE; k++) pe[k] = pack2(v[2*k], v[2*k+1]);
#pragma unroll
            for (int k = 0; k < NPE-1; k++) po[k] = pack2(v[2*k+1], v[2*k+2]);
#pragma unroll
            for (int j = 0; j < TS; j++){
                if (j & 1){
#pragma unroll
                    for (int p = 0; p < NPAIR; p++) fma2(a[p], po[p + (j>>1)], wd[j]);
                } else {
#pragma unroll
                    for (int p = 0; p < NPAIR; p++) fma2(a[p], pe[p + (j>>1)], wd[j]);
                }
            }
        }
        float* op = out + (((size_t)b*C + c0 + wrp)*OS + lane)*OS;
#pragma unroll
        for (int p = 0; p < NPAIR; p++){
            float2 f = unpk(a[p]);
            op[2*p] = f.x;
            if (2*p + 1 < OS) op[2*p + 1] = f.y;
        }
    }
}

// ---------------- launch (R15 schedule, exactly) ----------------
extern "C" void kernel_launch(void* const* d_in, const int* in_sizes, int n_in,
                              void* d_out, int out_size){
    const float* large  = (const float*)d_in[0];
    const float* medium = (const float*)d_in[1];
    const float* small  = (const float*)d_in[2];
    const float* search = (const float*)d_in[3];
    const float* wt  = (const float*)d_in[4];
    const float* bt  = (const float*)d_in[5];
    const float* gt  = (const float*)d_in[6];
    const float* bet = (const float*)d_in[7];
    const float* mt  = (const float*)d_in[8];
    const float* vt  = (const float*)d_in[9];
    const float* ws  = (const float*)d_in[10];
    const float* bs  = (const float*)d_in[11];
    const float* gs  = (const float*)d_in[12];
    const float* bes = (const float*)d_in[13];
    const float* ms  = (const float*)d_in[14];
    const float* vs  = (const float*)d_in[15];
    const float* w1  = (const float*)d_in[16];
    const float* b1  = (const float*)d_in[17];
    const float* g1  = (const float*)d_in[18];
    const float* be1 = (const float*)d_in[19];
    const float* m1  = (const float*)d_in[20];
    const float* v1  = (const float*)d_in[21];
    const float* w2  = (const float*)d_in[22];
    const float* b2  = (const float*)d_in[23];
    float* out = (float*)d_out;

    float *lf, *mf, *sf, *lc, *mc, *sc, *hp;
    cudaGetSymbolAddress((void**)&lf, g_lf);
    cudaGetSymbolAddress((void**)&mf, g_mf);
    cudaGetSymbolAddress((void**)&sf, g_sf);
    cudaGetSymbolAddress((void**)&lc, g_lc);
    cudaGetSymbolAddress((void**)&mc, g_mc);
    cudaGetSymbolAddress((void**)&sc, g_sc);
    cudaGetSymbolAddress((void**)&hp, g_hp);

    static cudaStream_t st1 = 0, st2 = 0;
    static cudaEvent_t evRoot = 0, evT = 0, evFork = 0, ev1 = 0, ev2 = 0;
    if (!st1){
        cudaStreamCreateWithFlags(&st1, cudaStreamNonBlocking);
        cudaStreamCreateWithFlags(&st2, cudaStreamNonBlocking);
        cudaEventCreateWithFlags(&evRoot, cudaEventDisableTiming);
        cudaEventCreateWithFlags(&evT, cudaEventDisableTiming);
        cudaEventCreateWithFlags(&evFork, cudaEventDisableTiming);
        cudaEventCreateWithFlags(&ev1, cudaEventDisableTiming);
        cudaEventCreateWithFlags(&ev2, cudaEventDisableTiming);
        cudaFuncSetAttribute(conv_search_mma,
                             cudaFuncAttributeMaxDynamicSharedMemorySize, CSM_BYTES);
    }

    prep_kernel<<<1, 256>>>(bt, gt, bet, mt, vt, bs, gs, bes, ms, vs, b1, g1, be1, m1, v1);

    // fork: tmpl_all on st1 concurrently with weight prep + conv on stream 0
    cudaEventRecord(evRoot, 0);
    cudaStreamWaitEvent(st1, evRoot, 0);
    tmpl_all<<<dim3(64, 4), 512, 0, st1>>>(large, medium, small, wt, lf, mf, sf);
    cudaEventRecord(evT, st1);

    wt_trans<<<(9*C*C + 255)/256, 256>>>(ws);
    w1_split<<<(C*C + 255)/256, 256>>>(w1);
    zero_hp<<<(HP_TOTAL + 255)/256, 256>>>();
    conv_search_mma<<<dim3(64, 7, 4), 256, CSM_BYTES>>>(search);
    cudaStreamWaitEvent(0, evT, 0);

    // fork three independent corr->head chains
    cudaEventRecord(evFork, 0);
    cudaStreamWaitEvent(st1, evFork, 0);
    cudaStreamWaitEvent(st2, evFork, 0);

    float* hp_l = hp;
    float* hp_m = hp + 64*729;
    float* hp_s = hp + 64*729 + 64*625;

    corr_v2<7, 2, 27><<<dim3(64, 32), 256>>>(lf, lc);
    head_mma<<<dim3(64, 6, 4), 256>>>(lc, 729, w2, hp_l);

    corr_v2<5, 0, 25><<<dim3(64, 32), 256, 0, st1>>>(mf, mc);
    head_mma<<<dim3(64, 5, 4), 256, 0, st1>>>(mc, 625, w2, hp_m);
    cudaEventRecord(ev1, st1);

    corr_v2<3, 0, 27><<<dim3(64, 32), 256, 0, st2>>>(sf, sc);
    head_mma<<<dim3(64, 6, 4), 256, 0, st2>>>(sc, 729, w2, hp_s);
    cudaEventRecord(ev2, st2);

    cudaStreamWaitEvent(0, ev1, 0);
    cudaStreamWaitEvent(0, ev2, 0);
    final_sig<<<(HP_TOTAL + 255)/256, 256>>>(b2, out);
}